// round 13
// baseline (speedup 1.0000x reference)
#include <cuda_runtime.h>
#include <cuda_bf16.h>
#include <math.h>
#include <stdint.h>

// Problem constants (fixed shapes per reference)
#define NN 4096
#define EE 256
#define KK 128
#define BB 64
#define DD 8

// ---------------- scratch (no allocations allowed) ----------------
__device__ float g_t0[NN * EE];
__device__ float g_hres[NN * EE];
__device__ float g_c[NN * KK];
__device__ float g_s[NN * KK];
__device__ float g_sfr[BB * KK * EE];
__device__ float g_sfi[BB * KK * EE];
__device__ float g_kf[KK * EE];
__device__ int   g_off[BB + 1];
// Activations, SLAB layout: 8 slabs [c][4096 rows][64 bf16 = 128B], SW128-swizzled.
__device__ __align__(128) __nv_bfloat16 g_x2a[NN * 512];
__device__ __align__(128) __nv_bfloat16 g_x2b[NN * 512];
// Weights, SLAB layout: 9 gemms x [nblk 4][c 8][64 rows][64 bf16], swizzled.
__device__ __align__(128) __nv_bfloat16 g_wc[9 * 256 * 512];

// ---------------- helpers ----------------
__device__ __forceinline__ float silu(float v) {
    return v / (1.0f + __expf(-v));
}

__device__ __forceinline__ uint32_t smem_u32(const void* p) {
    uint32_t a;
    asm("{ .reg .u64 t; cvta.to.shared.u64 t, %1; cvt.u32.u64 %0, t; }" : "=r"(a) : "l"(p));
    return a;
}

#define SWZ(o) ((o) ^ (((o) >> 3) & 0x70))

#define LDMATRIX_X4(r0, r1, r2, r3, addr) \
    asm volatile("ldmatrix.sync.aligned.m8n8.x4.shared.b16 {%0,%1,%2,%3}, [%4];" \
                 : "=r"(r0), "=r"(r1), "=r"(r2), "=r"(r3) : "r"(addr))

#define MMA_BF16(c, a, b0, b1) \
    asm volatile("mma.sync.aligned.m16n8k16.row.col.f32.bf16.bf16.f32 " \
                 "{%0,%1,%2,%3},{%4,%5,%6,%7},{%8,%9},{%0,%1,%2,%3};" \
                 : "+f"((c)[0]), "+f"((c)[1]), "+f"((c)[2]), "+f"((c)[3]) \
                 : "r"((a)[0]), "r"((a)[1]), "r"((a)[2]), "r"((a)[3]), \
                   "r"(b0), "r"(b1))

#define MBAR_INIT(a, c) \
    asm volatile("mbarrier.init.shared.b64 [%0], %1;" :: "r"(a), "r"((uint32_t)(c)) : "memory")

#define MBAR_EXPECT_TX(a, n) \
    asm volatile("mbarrier.arrive.expect_tx.shared.b64 _, [%0], %1;" \
                 :: "r"(a), "r"((uint32_t)(n)) : "memory")

#define MBAR_WAIT(addr, ph) do { \
    uint32_t _m = (addr), _p = (uint32_t)(ph), _d; \
    asm volatile("{\n\t.reg .pred p;\n\tmbarrier.try_wait.parity.acquire.cta.shared::cta.b64 p, [%1], %2;\n\tselp.b32 %0, 1, 0, p;\n\t}" \
        : "=r"(_d) : "r"(_m), "r"(_p) : "memory"); \
    if (!_d) { \
        asm volatile("{\n\t.reg .pred P1;\n\tWL_%=:\n\tmbarrier.try_wait.parity.acquire.cta.shared::cta.b64 P1, [%0], %1, 0x989680;\n\t@P1 bra.uni WD_%=;\n\tbra.uni WL_%=;\n\tWD_%=:\n\t}" \
            :: "r"(_m), "r"(_p) : "memory"); \
    } \
} while (0)

#define CP_BULK(dst, src, bytes, mbar) \
    asm volatile("cp.async.bulk.shared::cta.global.mbarrier::complete_tx::bytes " \
                 "[%0], [%1], %2, [%3];" \
                 :: "r"(dst), "l"(src), "r"((uint32_t)(bytes)), "r"(mbar) : "memory")

// packed fp32x2 FMA helpers (SASS FFMA2 — PTX-only pattern)
#define PACK2(dst, v) \
    asm("mov.b64 %0, {%1, %1};" : "=l"(dst) : "f"(v))
#define FMA2(acc, a, b) \
    asm("fma.rn.f32x2 %0, %1, %2, %0;" : "+l"(acc) : "l"(a), "l"(b))
#define UNPACK2(lo, hi, v) \
    asm("mov.b64 {%0, %1}, %2;" : "=f"(lo), "=f"(hi) : "l"(v))

// ============================================================================
// HMMA GEMM, W-persistent, bulk-copy loads (R9/R11 config — best measured)
// ============================================================================
#define ASLAB (4096 * 128)
#define A_ST  8192
#define W_PB  65536
#define GEMM_SMEM (W_PB + 3 * A_ST)  // 90112 -> 2 CTAs/SM

__global__ void __launch_bounds__(256, 2) gemm_mma_kernel(
    const __nv_bfloat16* __restrict__ A2,
    const __nv_bfloat16* __restrict__ Wc,
    const float* __restrict__ skip,
    float* __restrict__ outf,
    __nv_bfloat16* __restrict__ out2)
{
    extern __shared__ char smem[];
    uint32_t sb = smem_u32(smem);
    __shared__ __align__(8) uint64_t mbars[4];

    int tid = threadIdx.x, wid = tid >> 5, lane = tid & 31;
    int m0 = blockIdx.y * 64, n0 = blockIdx.x * 64;
    int nb = blockIdx.x;
    int warp_m = (wid & 1) * 32, warp_n = (wid >> 1) * 16;

    uint32_t mb[3] = { smem_u32(&mbars[0]), smem_u32(&mbars[1]), smem_u32(&mbars[2]) };
    uint32_t wbar  = smem_u32(&mbars[3]);

    if (tid == 0) {
        MBAR_INIT(mb[0], 1);
        MBAR_INIT(mb[1], 1);
        MBAR_INIT(mb[2], 1);
        MBAR_INIT(wbar, 1);
    }
    __syncthreads();

    const char* gA = (const char*)A2 + (size_t)m0 * 128;
    const char* gW = (const char*)Wc + (size_t)nb * W_PB;

    if (tid == 0) {
        MBAR_EXPECT_TX(wbar, W_PB);
        CP_BULK(sb, gW, W_PB, wbar);
        MBAR_EXPECT_TX(mb[0], A_ST);
        CP_BULK(sb + W_PB, gA + 0 * (size_t)ASLAB, A_ST, mb[0]);
        MBAR_EXPECT_TX(mb[1], A_ST);
        CP_BULK(sb + W_PB + A_ST, gA + 1 * (size_t)ASLAB, A_ST, mb[1]);
    }

    float acc[2][2][4];
#pragma unroll
    for (int i = 0; i < 2; i++)
#pragma unroll
        for (int j = 0; j < 2; j++)
#pragma unroll
            for (int q = 0; q < 4; q++) acc[i][j][q] = 0.f;

    int arow0 = warp_m + (lane & 15);
    int brow  = warp_n + (lane & 15);
    int hi16  = (lane >> 4) * 16;

    MBAR_WAIT(wbar, 0);

#pragma unroll
    for (int ch = 0; ch < 8; ch++) {
        if (ch + 2 < 8 && tid == 0) {
            int ns = (ch + 2) % 3;
            MBAR_EXPECT_TX(mb[ns], A_ST);
            CP_BULK(sb + W_PB + ns * A_ST, gA + (size_t)(ch + 2) * ASLAB, A_ST, mb[ns]);
        }

        const int s = ch % 3;
        MBAR_WAIT(mb[s], (ch / 3) & 1);

        uint32_t aB = sb + W_PB + s * A_ST;
        const bool isHi = (ch < 4);
        const uint32_t whiB = sb + (uint32_t)((isHi ? ch : (ch - 4)) * 8192);
        const uint32_t wloB = sb + (uint32_t)((4 + ch) * 8192);

        uint32_t a[2][2][4], bh[2][4], bl[2][4];
        {
            uint32_t o0 = SWZ((uint32_t)(arow0 * 128 + hi16));
            uint32_t o1 = SWZ((uint32_t)((arow0 + 16) * 128 + hi16));
            LDMATRIX_X4(a[0][0][0], a[0][0][1], a[0][0][2], a[0][0][3], aB + o0);
            LDMATRIX_X4(a[0][1][0], a[0][1][1], a[0][1][2], a[0][1][3], aB + o1);
            uint32_t bo = SWZ((uint32_t)(brow * 128 + hi16));
            LDMATRIX_X4(bh[0][0], bh[0][1], bh[0][2], bh[0][3], whiB + bo);
            if (isHi) LDMATRIX_X4(bl[0][0], bl[0][1], bl[0][2], bl[0][3], wloB + bo);
        }

#pragma unroll
        for (int kh = 0; kh < 4; kh++) {
            const int cur = kh & 1, nxt = cur ^ 1;
            if (kh < 3) {
                uint32_t ko = (uint32_t)((kh + 1) * 32 + hi16);
                uint32_t o0 = SWZ((uint32_t)(arow0 * 128) + ko);
                uint32_t o1 = SWZ((uint32_t)((arow0 + 16) * 128) + ko);
                LDMATRIX_X4(a[nxt][0][0], a[nxt][0][1], a[nxt][0][2], a[nxt][0][3], aB + o0);
                LDMATRIX_X4(a[nxt][1][0], a[nxt][1][1], a[nxt][1][2], a[nxt][1][3], aB + o1);
                uint32_t bo = SWZ((uint32_t)(brow * 128) + ko);
                LDMATRIX_X4(bh[nxt][0], bh[nxt][1], bh[nxt][2], bh[nxt][3], whiB + bo);
                if (isHi) LDMATRIX_X4(bl[nxt][0], bl[nxt][1], bl[nxt][2], bl[nxt][3], wloB + bo);
            }
#pragma unroll
            for (int mt = 0; mt < 2; mt++)
#pragma unroll
                for (int j = 0; j < 2; j++)
                    MMA_BF16(acc[mt][j], a[cur][mt], bh[cur][j], bh[cur][j + 2]);
            if (isHi) {
#pragma unroll
                for (int mt = 0; mt < 2; mt++)
#pragma unroll
                    for (int j = 0; j < 2; j++)
                        MMA_BF16(acc[mt][j], a[cur][mt], bl[cur][j], bl[cur][j + 2]);
            }
        }

        __syncthreads();
    }

    // ---------------- epilogue ----------------
    char* o2 = (char*)out2;
    int r0 = lane >> 2, cp = (lane & 3) * 2;
#pragma unroll
    for (int mt = 0; mt < 2; mt++) {
#pragma unroll
        for (int j = 0; j < 2; j++) {
            int n = n0 + warp_n + j * 8 + cp;
#pragma unroll
            for (int half = 0; half < 2; half++) {
                int m = m0 + warp_m + mt * 16 + r0 + half * 8;
                float v0 = acc[mt][j][half * 2 + 0];
                float v1 = acc[mt][j][half * 2 + 1];
                v0 = silu(v0);
                v1 = silu(v1);
                if (skip) {
                    float2 sk = *reinterpret_cast<const float2*>(skip + (size_t)m * 256 + n);
                    v0 += sk.x; v1 += sk.y;
                }
                if (outf) {
                    float2 o; o.x = v0; o.y = v1;
                    *reinterpret_cast<float2*>(outf + (size_t)m * 256 + n) = o;
                }
                if (out2) {
                    __nv_bfloat16 h0 = __float2bfloat16(v0);
                    __nv_bfloat16 h1 = __float2bfloat16(v1);
                    __nv_bfloat162 hh; hh.x = h0; hh.y = h1;
                    __nv_bfloat162 ll;
                    ll.x = __float2bfloat16(v0 - __bfloat162float(h0));
                    ll.y = __float2bfloat16(v1 - __bfloat162float(h1));
                    uint32_t loc = SWZ((uint32_t)(m * 128 + (n & 63) * 2));
                    *reinterpret_cast<__nv_bfloat162*>(
                        o2 + (size_t)(n >> 6) * ASLAB + loc) = hh;
                    *reinterpret_cast<__nv_bfloat162*>(
                        o2 + (size_t)(4 + (n >> 6)) * ASLAB + loc) = ll;
                }
            }
        }
    }
}

// ---------------- hi/lo conversion of h (slabbed, swizzled) ----------------
__global__ void conv_h_kernel(const float* __restrict__ h) {
    int idx = blockIdx.x * 256 + threadIdx.x;
    int m = idx >> 8, e = idx & 255;
    float v = h[idx];
    __nv_bfloat16 hi = __float2bfloat16(v);
    __nv_bfloat16 lo = __float2bfloat16(v - __bfloat162float(hi));
    uint32_t loc = SWZ((uint32_t)(m * 128 + (e & 63) * 2));
    char* base = (char*)g_x2a;
    *reinterpret_cast<__nv_bfloat16*>(base + (size_t)(e >> 6) * ASLAB + loc) = hi;
    *reinterpret_cast<__nv_bfloat16*>(base + (size_t)(4 + (e >> 6)) * ASLAB + loc) = lo;
}

// ---------------- weight conversion (slabbed, swizzled) ----------------
__global__ void conv_w_kernel(const float* __restrict__ Wpre,
                              const float* __restrict__ W0,
                              const float* __restrict__ Wres) {
    int g = blockIdx.y;
    int i = blockIdx.x * 256 + threadIdx.x;
    int n = i >> 8, k = i & 255;
    const float* src = (g < 2) ? (Wpre + (size_t)g * 65536)
                     : (g == 2) ? W0
                     : (Wres + (size_t)(g - 3) * 65536);
    float v = src[i];
    __nv_bfloat16 hi = __float2bfloat16(v);
    __nv_bfloat16 lo = __float2bfloat16(v - __bfloat162float(hi));
    uint32_t loc = SWZ((uint32_t)((n & 63) * 128 + (k & 63) * 2));
    char* base = (char*)g_wc + (size_t)g * 262144 + (size_t)(n >> 6) * W_PB;
    *reinterpret_cast<__nv_bfloat16*>(base + (size_t)(k >> 6) * 8192 + loc) = hi;
    *reinterpret_cast<__nv_bfloat16*>(base + (size_t)(4 + (k >> 6)) * 8192 + loc) = lo;
}

// ---------------- segment offsets from sorted batch_seg ----------------
__global__ void seg_offsets_kernel(const int* __restrict__ seg) {
    int n = blockIdx.x * blockDim.x + threadIdx.x;
    if (n >= NN) return;
    int s = seg[n];
    if (n == 0) {
        for (int b = 0; b <= s; b++) g_off[b] = 0;
    } else {
        int p = seg[n - 1];
        for (int b = p + 1; b <= s; b++) g_off[b] = n;
    }
    if (n == NN - 1) {
        for (int b = s + 1; b <= BB; b++) g_off[b] = NN;
    }
}

// ---------------- dot products + cos/sin ----------------
__global__ void dot_kernel(const float* __restrict__ x,
                           const float* __restrict__ kvec,
                           const int* __restrict__ seg,
                           float* __restrict__ dot_out) {
    int n = blockIdx.x;
    int kk = threadIdx.x;
    int b = seg[n];
    float x0 = x[n * 3 + 0], x1 = x[n * 3 + 1], x2 = x[n * 3 + 2];
    const float* kr = kvec + ((size_t)b * KK + kk) * 3;
    float d = kr[0] * x0 + kr[1] * x1 + kr[2] * x2;
    dot_out[n * KK + kk] = d;
    float cv, sv;
    sincosf(d, &sv, &cv);
    g_c[n * KK + kk] = cv;
    g_s[n * KK + kk] = sv;
}

// ---------------- low-rank k-filter ----------------
__global__ void kf_kernel(const float* __restrict__ Wup,
                          const float* __restrict__ Wdn) {
    int e = threadIdx.x;
    int k = blockIdx.x;
    float a = 0.f;
#pragma unroll
    for (int d = 0; d < DD; d++) a += Wup[e * DD + d] * Wdn[d * KK + k];
    g_kf[k * EE + e] = a;
}

// ---------------- structure factors v2: tile k32 x e128, thread k2 x e8 -----
// 16 independent FMA2 chains per thread; c/s tile reloads 8x -> 2x.
__global__ void __launch_bounds__(256, 3) sf_kernel() {
    int b  = blockIdx.z;
    int k0 = blockIdx.y * 32;
    int e0 = blockIdx.x * 128;
    int t = threadIdx.x;
    int ep = t & 15;   // e-oct: e = e0 + ep*8 .. +8
    int kp = t >> 4;   // k-pair: k = k0 + kp*2 + {0,1}
    __shared__ float csh[32][32], ssh[32][32];
    __shared__ __align__(16) float hsh[32][128];
    int st = g_off[b], en = g_off[b + 1];

    uint64_t aR0[4] = {0, 0, 0, 0}, aR1[4] = {0, 0, 0, 0};
    uint64_t aI0[4] = {0, 0, 0, 0}, aI1[4] = {0, 0, 0, 0};
    uint32_t hbase = smem_u32(&hsh[0][0]) + ep * 32;

    for (int n0 = st; n0 < en; n0 += 32) {
#pragma unroll
        for (int l = 0; l < 4; l++) {
            int idx = t + 256 * l;
            int r = idx >> 5, c = idx & 31;
            int n = n0 + r;
            bool v = (n < en);
            csh[r][c] = v ? g_c[n * KK + k0 + c] : 0.f;
            ssh[r][c] = v ? g_s[n * KK + k0 + c] : 0.f;
        }
#pragma unroll
        for (int l = 0; l < 4; l++) {
            int idx = t + 256 * l;          // float4 slot 0..1023
            int r = idx >> 5, c4 = idx & 31;
            int n = n0 + r;
            float4 hv = (n < en)
                ? *reinterpret_cast<const float4*>(&g_hres[(size_t)n * EE + e0 + c4 * 4])
                : make_float4(0.f, 0.f, 0.f, 0.f);
            *reinterpret_cast<float4*>(&hsh[r][c4 * 4]) = hv;
        }
        __syncthreads();
#pragma unroll
        for (int nn = 0; nn < 32; nn++) {
            uint64_t h01, h23, h45, h67;
            asm volatile("ld.shared.v2.u64 {%0, %1}, [%2];"
                         : "=l"(h01), "=l"(h23) : "r"(hbase + nn * 512));
            asm volatile("ld.shared.v2.u64 {%0, %1}, [%2];"
                         : "=l"(h45), "=l"(h67) : "r"(hbase + nn * 512 + 16));
            float c0 = csh[nn][kp * 2], c1 = csh[nn][kp * 2 + 1];
            float s0 = ssh[nn][kp * 2], s1 = ssh[nn][kp * 2 + 1];
            uint64_t c02, c12, s02, s12;
            PACK2(c02, c0); PACK2(c12, c1); PACK2(s02, s0); PACK2(s12, s1);
            FMA2(aR0[0], c02, h01); FMA2(aR0[1], c02, h23);
            FMA2(aR0[2], c02, h45); FMA2(aR0[3], c02, h67);
            FMA2(aR1[0], c12, h01); FMA2(aR1[1], c12, h23);
            FMA2(aR1[2], c12, h45); FMA2(aR1[3], c12, h67);
            FMA2(aI0[0], s02, h01); FMA2(aI0[1], s02, h23);
            FMA2(aI0[2], s02, h45); FMA2(aI0[3], s02, h67);
            FMA2(aI1[0], s12, h01); FMA2(aI1[1], s12, h23);
            FMA2(aI1[2], s12, h45); FMA2(aI1[3], s12, h67);
        }
        __syncthreads();
    }

    // epilogue: 2 k rows x 8 e, kfilter folded in
#pragma unroll
    for (int kk = 0; kk < 2; kk++) {
        int k = k0 + kp * 2 + kk;
        float vR[8], vI[8];
        if (kk == 0) {
            UNPACK2(vR[0], vR[1], aR0[0]); UNPACK2(vR[2], vR[3], aR0[1]);
            UNPACK2(vR[4], vR[5], aR0[2]); UNPACK2(vR[6], vR[7], aR0[3]);
            UNPACK2(vI[0], vI[1], aI0[0]); UNPACK2(vI[2], vI[3], aI0[1]);
            UNPACK2(vI[4], vI[5], aI0[2]); UNPACK2(vI[6], vI[7], aI0[3]);
        } else {
            UNPACK2(vR[0], vR[1], aR1[0]); UNPACK2(vR[2], vR[3], aR1[1]);
            UNPACK2(vR[4], vR[5], aR1[2]); UNPACK2(vR[6], vR[7], aR1[3]);
            UNPACK2(vI[0], vI[1], aI1[0]); UNPACK2(vI[2], vI[3], aI1[1]);
            UNPACK2(vI[4], vI[5], aI1[2]); UNPACK2(vI[6], vI[7], aI1[3]);
        }
        const float* kfp = &g_kf[(size_t)k * EE + e0 + ep * 8];
        float4 f0 = *reinterpret_cast<const float4*>(kfp);
        float4 f1 = *reinterpret_cast<const float4*>(kfp + 4);
        size_t idx = ((size_t)b * KK + k) * EE + e0 + ep * 8;
        float4 oR0, oR1, oI0, oI1;
        oR0.x = vR[0] * f0.x; oR0.y = vR[1] * f0.y; oR0.z = vR[2] * f0.z; oR0.w = vR[3] * f0.w;
        oR1.x = vR[4] * f1.x; oR1.y = vR[5] * f1.y; oR1.z = vR[6] * f1.z; oR1.w = vR[7] * f1.w;
        oI0.x = vI[0] * f0.x; oI0.y = vI[1] * f0.y; oI0.z = vI[2] * f0.z; oI0.w = vI[3] * f0.w;
        oI1.x = vI[4] * f1.x; oI1.y = vI[5] * f1.y; oI1.z = vI[6] * f1.z; oI1.w = vI[7] * f1.w;
        *reinterpret_cast<float4*>(&g_sfr[idx])     = oR0;
        *reinterpret_cast<float4*>(&g_sfr[idx + 4]) = oR1;
        *reinterpret_cast<float4*>(&g_sfi[idx])     = oI0;
        *reinterpret_cast<float4*>(&g_sfi[idx + 4]) = oI1;
    }
}

// ---------------- back-projection v2: tile n32 x e64, thread e8 -------------
// 8 independent FMA2 chains (separate R/I accumulators, merged at end).
__global__ void __launch_bounds__(256, 3) hupd_kernel(const int* __restrict__ seg) {
    int n0 = blockIdx.y * 32;
    int e0 = blockIdx.x * 64;
    int t = threadIdx.x;
    int ep = t & 7;     // e = e0 + ep*8 .. +8
    int ny = t >> 3;
    int n = n0 + ny;
    int b = seg[n];
    __shared__ float csh[32][32], ssh[32][32];
    uint64_t accR[4] = {0, 0, 0, 0}, accI[4] = {0, 0, 0, 0};

    for (int k0c = 0; k0c < KK; k0c += 32) {
#pragma unroll
        for (int l = 0; l < 4; l++) {
            int idx = t + 256 * l;
            int r = idx >> 5, c = idx & 31;
            csh[r][c] = g_c[(n0 + r) * KK + k0c + c];
            ssh[r][c] = g_s[(n0 + r) * KK + k0c + c];
        }
        __syncthreads();
        const char* baseR = (const char*)(g_sfr + ((size_t)b * KK + k0c) * EE + e0 + ep * 8);
        const char* baseI = (const char*)(g_sfi + ((size_t)b * KK + k0c) * EE + e0 + ep * 8);
#pragma unroll
        for (int kk = 0; kk < 32; kk++) {
            float cv = csh[ny][kk];
            float sv = ssh[ny][kk];
            uint64_t cv2, sv2;
            PACK2(cv2, cv);
            PACK2(sv2, sv);
            ulonglong2 pr0 = *reinterpret_cast<const ulonglong2*>(baseR + (size_t)kk * (EE * 4));
            ulonglong2 pr1 = *reinterpret_cast<const ulonglong2*>(baseR + (size_t)kk * (EE * 4) + 16);
            ulonglong2 pi0 = *reinterpret_cast<const ulonglong2*>(baseI + (size_t)kk * (EE * 4));
            ulonglong2 pi1 = *reinterpret_cast<const ulonglong2*>(baseI + (size_t)kk * (EE * 4) + 16);
            FMA2(accR[0], cv2, pr0.x); FMA2(accR[1], cv2, pr0.y);
            FMA2(accR[2], cv2, pr1.x); FMA2(accR[3], cv2, pr1.y);
            FMA2(accI[0], sv2, pi0.x); FMA2(accI[1], sv2, pi0.y);
            FMA2(accI[2], sv2, pi1.x); FMA2(accI[3], sv2, pi1.y);
        }
        __syncthreads();
    }

    float vR[8], vI[8];
    UNPACK2(vR[0], vR[1], accR[0]); UNPACK2(vR[2], vR[3], accR[1]);
    UNPACK2(vR[4], vR[5], accR[2]); UNPACK2(vR[6], vR[7], accR[3]);
    UNPACK2(vI[0], vI[1], accI[0]); UNPACK2(vI[2], vI[3], accI[1]);
    UNPACK2(vI[4], vI[5], accI[2]); UNPACK2(vI[6], vI[7], accI[3]);

    __nv_bfloat16 hi[8], lo[8];
#pragma unroll
    for (int q = 0; q < 8; q++) {
        float v = 0.01f * (vR[q] + vI[q]);
        hi[q] = __float2bfloat16(v);
        lo[q] = __float2bfloat16(v - __bfloat162float(hi[q]));
    }
    int e = e0 + ep * 8;
    uint32_t loc = SWZ((uint32_t)(n * 128 + (e & 63) * 2));
    char* base = (char*)g_x2a;
    *reinterpret_cast<uint4*>(base + (size_t)(e >> 6) * ASLAB + loc) =
        *reinterpret_cast<uint4*>(hi);
    *reinterpret_cast<uint4*>(base + (size_t)(4 + (e >> 6)) * ASLAB + loc) =
        *reinterpret_cast<uint4*>(lo);
}

// ---------------- launch ----------------
extern "C" void kernel_launch(void* const* d_in, const int* in_sizes, int n_in,
                              void* d_out, int out_size) {
    const float *h = nullptr, *x = nullptr, *kv = nullptr;
    const float *Wpre = nullptr, *Wdn = nullptr, *Wup = nullptr;
    const float *W0 = nullptr, *Wres = nullptr;
    const int* seg = nullptr;

    for (int i = 0; i < n_in; i++) {
        switch (in_sizes[i]) {
            case NN * EE:           h    = (const float*)d_in[i]; break;
            case NN * 3:            x    = (const float*)d_in[i]; break;
            case BB * KK * 3:       kv   = (const float*)d_in[i]; break;
            case NN:                seg  = (const int*)d_in[i];   break;
            case 2 * EE * EE:       Wpre = (const float*)d_in[i]; break;
            case DD * KK:           Wdn  = (const float*)d_in[i]; break;
            case EE * DD:           Wup  = (const float*)d_in[i]; break;
            case EE * EE:           W0   = (const float*)d_in[i]; break;
            case 3 * 2 * EE * EE:   Wres = (const float*)d_in[i]; break;
            default: break;
        }
    }

    float* out = (float*)d_out;
    float* out_hu  = out;            // (NN, EE)
    float* out_dot = out + NN * EE;  // (NN, KK)

    float *t0, *hres;
    __nv_bfloat16 *x2a, *x2b, *wc;
    cudaGetSymbolAddress((void**)&t0,   g_t0);
    cudaGetSymbolAddress((void**)&hres, g_hres);
    cudaGetSymbolAddress((void**)&x2a,  g_x2a);
    cudaGetSymbolAddress((void**)&x2b,  g_x2b);
    cudaGetSymbolAddress((void**)&wc,   g_wc);

    cudaFuncSetAttribute(gemm_mma_kernel,
                         cudaFuncAttributeMaxDynamicSharedMemorySize, GEMM_SMEM);
    dim3 ggrid(EE / 64, NN / 64);  // (4, 64) = 256 CTAs -> 2/SM

    // conversions
    conv_w_kernel<<<dim3(256, 9), 256>>>(Wpre, W0, Wres);
    conv_h_kernel<<<NN * EE / 256, 256>>>(h);

    // pre-residual: x2b = silu(h@W0'), hres = h + silu(x2b@W1')
    gemm_mma_kernel<<<ggrid, 256, GEMM_SMEM>>>(x2a, wc + 0 * 131072, nullptr, nullptr, x2b);
    gemm_mma_kernel<<<ggrid, 256, GEMM_SMEM>>>(x2b, wc + 1 * 131072, h, hres, nullptr);

    // Ewald geometry path
    seg_offsets_kernel<<<(NN + 255) / 256, 256>>>(seg);
    dot_kernel<<<NN, KK>>>(x, kv, seg, out_dot);
    kf_kernel<<<KK, EE>>>(Wup, Wdn);
    sf_kernel<<<dim3(EE / 128, KK / 32, BB), 256>>>();
    hupd_kernel<<<dim3(EE / 64, NN / 32), 256>>>(seg);  // -> g_x2a (slabbed hi/lo)

    // update MLP: t0 = silu(hu @ W0^T)
    gemm_mma_kernel<<<ggrid, 256, GEMM_SMEM>>>(x2a, wc + 2 * 131072, nullptr, t0, x2b);

    // 3 residual blocks
    for (int i = 0; i < 3; i++) {
        const __nv_bfloat16* wa = wc + (size_t)(3 + 2 * i) * 131072;
        const __nv_bfloat16* wb = wc + (size_t)(4 + 2 * i) * 131072;
        gemm_mma_kernel<<<ggrid, 256, GEMM_SMEM>>>(x2b, wa, nullptr, nullptr, x2a);
        float* dstf = (i == 2) ? out_hu : t0;
        __nv_bfloat16* dst2 = (i == 2) ? nullptr : x2b;
        gemm_mma_kernel<<<ggrid, 256, GEMM_SMEM>>>(x2a, wb, t0, dstf, dst2);
    }
}

// round 14
// speedup vs baseline: 1.1971x; 1.1971x over previous
#include <cuda_runtime.h>
#include <cuda_bf16.h>
#include <math.h>
#include <stdint.h>

// Problem constants (fixed shapes per reference)
#define NN 4096
#define EE 256
#define KK 128
#define BB 64
#define DD 8

// ---------------- scratch (no allocations allowed) ----------------
__device__ float g_t0[NN * EE];
__device__ float g_hres[NN * EE];
__device__ float g_c[NN * KK];
__device__ float g_s[NN * KK];
__device__ float g_sfr[BB * KK * EE];
__device__ float g_sfi[BB * KK * EE];
__device__ float g_kf[KK * EE];
__device__ int   g_off[BB + 1];
// Activations, SLAB layout: 8 slabs [c][4096 rows][64 bf16 = 128B], SW128-swizzled.
__device__ __align__(128) __nv_bfloat16 g_x2a[NN * 512];
__device__ __align__(128) __nv_bfloat16 g_x2b[NN * 512];
// Weights, SLAB layout: 9 gemms x [nblk 4][c 8][64 rows][64 bf16], swizzled.
__device__ __align__(128) __nv_bfloat16 g_wc[9 * 256 * 512];

// ---------------- helpers ----------------
__device__ __forceinline__ float silu(float v) {
    return v / (1.0f + __expf(-v));
}

__device__ __forceinline__ uint32_t smem_u32(const void* p) {
    uint32_t a;
    asm("{ .reg .u64 t; cvta.to.shared.u64 t, %1; cvt.u32.u64 %0, t; }" : "=r"(a) : "l"(p));
    return a;
}

#define SWZ(o) ((o) ^ (((o) >> 3) & 0x70))

#define LDMATRIX_X4(r0, r1, r2, r3, addr) \
    asm volatile("ldmatrix.sync.aligned.m8n8.x4.shared.b16 {%0,%1,%2,%3}, [%4];" \
                 : "=r"(r0), "=r"(r1), "=r"(r2), "=r"(r3) : "r"(addr))

#define MMA_BF16(c, a, b0, b1) \
    asm volatile("mma.sync.aligned.m16n8k16.row.col.f32.bf16.bf16.f32 " \
                 "{%0,%1,%2,%3},{%4,%5,%6,%7},{%8,%9},{%0,%1,%2,%3};" \
                 : "+f"((c)[0]), "+f"((c)[1]), "+f"((c)[2]), "+f"((c)[3]) \
                 : "r"((a)[0]), "r"((a)[1]), "r"((a)[2]), "r"((a)[3]), \
                   "r"(b0), "r"(b1))

#define MBAR_INIT(a, c) \
    asm volatile("mbarrier.init.shared.b64 [%0], %1;" :: "r"(a), "r"((uint32_t)(c)) : "memory")

#define MBAR_EXPECT_TX(a, n) \
    asm volatile("mbarrier.arrive.expect_tx.shared.b64 _, [%0], %1;" \
                 :: "r"(a), "r"((uint32_t)(n)) : "memory")

#define MBAR_WAIT(addr, ph) do { \
    uint32_t _m = (addr), _p = (uint32_t)(ph), _d; \
    asm volatile("{\n\t.reg .pred p;\n\tmbarrier.try_wait.parity.acquire.cta.shared::cta.b64 p, [%1], %2;\n\tselp.b32 %0, 1, 0, p;\n\t}" \
        : "=r"(_d) : "r"(_m), "r"(_p) : "memory"); \
    if (!_d) { \
        asm volatile("{\n\t.reg .pred P1;\n\tWL_%=:\n\tmbarrier.try_wait.parity.acquire.cta.shared::cta.b64 P1, [%0], %1, 0x989680;\n\t@P1 bra.uni WD_%=;\n\tbra.uni WL_%=;\n\tWD_%=:\n\t}" \
            :: "r"(_m), "r"(_p) : "memory"); \
    } \
} while (0)

#define CP_BULK(dst, src, bytes, mbar) \
    asm volatile("cp.async.bulk.shared::cta.global.mbarrier::complete_tx::bytes " \
                 "[%0], [%1], %2, [%3];" \
                 :: "r"(dst), "l"(src), "r"((uint32_t)(bytes)), "r"(mbar) : "memory")

// packed fp32x2 FMA helpers (SASS FFMA2 — PTX-only pattern)
#define PACK2(dst, v) \
    asm("mov.b64 %0, {%1, %1};" : "=l"(dst) : "f"(v))
#define FMA2(acc, a, b) \
    asm("fma.rn.f32x2 %0, %1, %2, %0;" : "+l"(acc) : "l"(a), "l"(b))
#define UNPACK2(lo, hi, v) \
    asm("mov.b64 {%0, %1}, %2;" : "=f"(lo), "=f"(hi) : "l"(v))

// ============================================================================
// HMMA GEMM, W-persistent, bulk-copy loads (R9/R11 config — best measured)
// ============================================================================
#define ASLAB (4096 * 128)
#define A_ST  8192
#define W_PB  65536
#define GEMM_SMEM (W_PB + 3 * A_ST)  // 90112 -> 2 CTAs/SM

__global__ void __launch_bounds__(256, 2) gemm_mma_kernel(
    const __nv_bfloat16* __restrict__ A2,
    const __nv_bfloat16* __restrict__ Wc,
    const float* __restrict__ skip,
    float* __restrict__ outf,
    __nv_bfloat16* __restrict__ out2)
{
    extern __shared__ char smem[];
    uint32_t sb = smem_u32(smem);
    __shared__ __align__(8) uint64_t mbars[4];

    int tid = threadIdx.x, wid = tid >> 5, lane = tid & 31;
    int m0 = blockIdx.y * 64, n0 = blockIdx.x * 64;
    int nb = blockIdx.x;
    int warp_m = (wid & 1) * 32, warp_n = (wid >> 1) * 16;

    uint32_t mb[3] = { smem_u32(&mbars[0]), smem_u32(&mbars[1]), smem_u32(&mbars[2]) };
    uint32_t wbar  = smem_u32(&mbars[3]);

    if (tid == 0) {
        MBAR_INIT(mb[0], 1);
        MBAR_INIT(mb[1], 1);
        MBAR_INIT(mb[2], 1);
        MBAR_INIT(wbar, 1);
    }
    __syncthreads();

    const char* gA = (const char*)A2 + (size_t)m0 * 128;
    const char* gW = (const char*)Wc + (size_t)nb * W_PB;

    if (tid == 0) {
        MBAR_EXPECT_TX(wbar, W_PB);
        CP_BULK(sb, gW, W_PB, wbar);
        MBAR_EXPECT_TX(mb[0], A_ST);
        CP_BULK(sb + W_PB, gA + 0 * (size_t)ASLAB, A_ST, mb[0]);
        MBAR_EXPECT_TX(mb[1], A_ST);
        CP_BULK(sb + W_PB + A_ST, gA + 1 * (size_t)ASLAB, A_ST, mb[1]);
    }

    float acc[2][2][4];
#pragma unroll
    for (int i = 0; i < 2; i++)
#pragma unroll
        for (int j = 0; j < 2; j++)
#pragma unroll
            for (int q = 0; q < 4; q++) acc[i][j][q] = 0.f;

    int arow0 = warp_m + (lane & 15);
    int brow  = warp_n + (lane & 15);
    int hi16  = (lane >> 4) * 16;

    MBAR_WAIT(wbar, 0);

#pragma unroll
    for (int ch = 0; ch < 8; ch++) {
        if (ch + 2 < 8 && tid == 0) {
            int ns = (ch + 2) % 3;
            MBAR_EXPECT_TX(mb[ns], A_ST);
            CP_BULK(sb + W_PB + ns * A_ST, gA + (size_t)(ch + 2) * ASLAB, A_ST, mb[ns]);
        }

        const int s = ch % 3;
        MBAR_WAIT(mb[s], (ch / 3) & 1);

        uint32_t aB = sb + W_PB + s * A_ST;
        const bool isHi = (ch < 4);
        const uint32_t whiB = sb + (uint32_t)((isHi ? ch : (ch - 4)) * 8192);
        const uint32_t wloB = sb + (uint32_t)((4 + ch) * 8192);

        uint32_t a[2][2][4], bh[2][4], bl[2][4];
        {
            uint32_t o0 = SWZ((uint32_t)(arow0 * 128 + hi16));
            uint32_t o1 = SWZ((uint32_t)((arow0 + 16) * 128 + hi16));
            LDMATRIX_X4(a[0][0][0], a[0][0][1], a[0][0][2], a[0][0][3], aB + o0);
            LDMATRIX_X4(a[0][1][0], a[0][1][1], a[0][1][2], a[0][1][3], aB + o1);
            uint32_t bo = SWZ((uint32_t)(brow * 128 + hi16));
            LDMATRIX_X4(bh[0][0], bh[0][1], bh[0][2], bh[0][3], whiB + bo);
            if (isHi) LDMATRIX_X4(bl[0][0], bl[0][1], bl[0][2], bl[0][3], wloB + bo);
        }

#pragma unroll
        for (int kh = 0; kh < 4; kh++) {
            const int cur = kh & 1, nxt = cur ^ 1;
            if (kh < 3) {
                uint32_t ko = (uint32_t)((kh + 1) * 32 + hi16);
                uint32_t o0 = SWZ((uint32_t)(arow0 * 128) + ko);
                uint32_t o1 = SWZ((uint32_t)((arow0 + 16) * 128) + ko);
                LDMATRIX_X4(a[nxt][0][0], a[nxt][0][1], a[nxt][0][2], a[nxt][0][3], aB + o0);
                LDMATRIX_X4(a[nxt][1][0], a[nxt][1][1], a[nxt][1][2], a[nxt][1][3], aB + o1);
                uint32_t bo = SWZ((uint32_t)(brow * 128) + ko);
                LDMATRIX_X4(bh[nxt][0], bh[nxt][1], bh[nxt][2], bh[nxt][3], whiB + bo);
                if (isHi) LDMATRIX_X4(bl[nxt][0], bl[nxt][1], bl[nxt][2], bl[nxt][3], wloB + bo);
            }
#pragma unroll
            for (int mt = 0; mt < 2; mt++)
#pragma unroll
                for (int j = 0; j < 2; j++)
                    MMA_BF16(acc[mt][j], a[cur][mt], bh[cur][j], bh[cur][j + 2]);
            if (isHi) {
#pragma unroll
                for (int mt = 0; mt < 2; mt++)
#pragma unroll
                    for (int j = 0; j < 2; j++)
                        MMA_BF16(acc[mt][j], a[cur][mt], bl[cur][j], bl[cur][j + 2]);
            }
        }

        __syncthreads();
    }

    // ---------------- epilogue ----------------
    char* o2 = (char*)out2;
    int r0 = lane >> 2, cp = (lane & 3) * 2;
#pragma unroll
    for (int mt = 0; mt < 2; mt++) {
#pragma unroll
        for (int j = 0; j < 2; j++) {
            int n = n0 + warp_n + j * 8 + cp;
#pragma unroll
            for (int half = 0; half < 2; half++) {
                int m = m0 + warp_m + mt * 16 + r0 + half * 8;
                float v0 = acc[mt][j][half * 2 + 0];
                float v1 = acc[mt][j][half * 2 + 1];
                v0 = silu(v0);
                v1 = silu(v1);
                if (skip) {
                    float2 sk = *reinterpret_cast<const float2*>(skip + (size_t)m * 256 + n);
                    v0 += sk.x; v1 += sk.y;
                }
                if (outf) {
                    float2 o; o.x = v0; o.y = v1;
                    *reinterpret_cast<float2*>(outf + (size_t)m * 256 + n) = o;
                }
                if (out2) {
                    __nv_bfloat16 h0 = __float2bfloat16(v0);
                    __nv_bfloat16 h1 = __float2bfloat16(v1);
                    __nv_bfloat162 hh; hh.x = h0; hh.y = h1;
                    __nv_bfloat162 ll;
                    ll.x = __float2bfloat16(v0 - __bfloat162float(h0));
                    ll.y = __float2bfloat16(v1 - __bfloat162float(h1));
                    uint32_t loc = SWZ((uint32_t)(m * 128 + (n & 63) * 2));
                    *reinterpret_cast<__nv_bfloat162*>(
                        o2 + (size_t)(n >> 6) * ASLAB + loc) = hh;
                    *reinterpret_cast<__nv_bfloat162*>(
                        o2 + (size_t)(4 + (n >> 6)) * ASLAB + loc) = ll;
                }
            }
        }
    }
}

// ---------------- fused conversions: conv_w (2304 blocks) + conv_h (4096) ---
__global__ void conv_fused_kernel(const float* __restrict__ Wpre,
                                  const float* __restrict__ W0,
                                  const float* __restrict__ Wres,
                                  const float* __restrict__ h) {
    int bid = blockIdx.x;
    int tid = threadIdx.x;
    if (bid < 2304) {
        int g = bid >> 8;
        int i = (bid & 255) * 256 + tid;
        int n = i >> 8, k = i & 255;
        const float* src = (g < 2) ? (Wpre + (size_t)g * 65536)
                         : (g == 2) ? W0
                         : (Wres + (size_t)(g - 3) * 65536);
        float v = src[i];
        __nv_bfloat16 hi = __float2bfloat16(v);
        __nv_bfloat16 lo = __float2bfloat16(v - __bfloat162float(hi));
        uint32_t loc = SWZ((uint32_t)((n & 63) * 128 + (k & 63) * 2));
        char* base = (char*)g_wc + (size_t)g * 262144 + (size_t)(n >> 6) * W_PB;
        *reinterpret_cast<__nv_bfloat16*>(base + (size_t)(k >> 6) * 8192 + loc) = hi;
        *reinterpret_cast<__nv_bfloat16*>(base + (size_t)(4 + (k >> 6)) * 8192 + loc) = lo;
    } else {
        int idx = (bid - 2304) * 256 + tid;
        int m = idx >> 8, e = idx & 255;
        float v = h[idx];
        __nv_bfloat16 hi = __float2bfloat16(v);
        __nv_bfloat16 lo = __float2bfloat16(v - __bfloat162float(hi));
        uint32_t loc = SWZ((uint32_t)(m * 128 + (e & 63) * 2));
        char* base = (char*)g_x2a;
        *reinterpret_cast<__nv_bfloat16*>(base + (size_t)(e >> 6) * ASLAB + loc) = hi;
        *reinterpret_cast<__nv_bfloat16*>(base + (size_t)(4 + (e >> 6)) * ASLAB + loc) = lo;
    }
}

// ---------------- fused prep: dot (2048) + kf (128) + seg offsets (16) ------
__global__ void prep_kernel(const float* __restrict__ x,
                            const float* __restrict__ kvec,
                            const int* __restrict__ seg,
                            const float* __restrict__ Wup,
                            const float* __restrict__ Wdn,
                            float* __restrict__ dot_out) {
    int bid = blockIdx.x;
    int tid = threadIdx.x;
    if (bid < 2048) {
        int n = bid * 2 + (tid >> 7);
        int kk = tid & 127;
        int b = seg[n];
        float x0 = x[n * 3 + 0], x1 = x[n * 3 + 1], x2 = x[n * 3 + 2];
        const float* kr = kvec + ((size_t)b * KK + kk) * 3;
        float d = kr[0] * x0 + kr[1] * x1 + kr[2] * x2;
        dot_out[n * KK + kk] = d;
        float cv, sv;
        sincosf(d, &sv, &cv);
        g_c[n * KK + kk] = cv;
        g_s[n * KK + kk] = sv;
    } else if (bid < 2176) {
        int k = bid - 2048;
        int e = tid;
        float a = 0.f;
#pragma unroll
        for (int d = 0; d < DD; d++) a += Wup[e * DD + d] * Wdn[d * KK + k];
        g_kf[k * EE + e] = a;
    } else {
        int n = (bid - 2176) * 256 + tid;
        int s = seg[n];
        if (n == 0) {
            for (int b = 0; b <= s; b++) g_off[b] = 0;
        } else {
            int p = seg[n - 1];
            for (int b = p + 1; b <= s; b++) g_off[b] = n;
        }
        if (n == NN - 1) {
            for (int b = s + 1; b <= BB; b++) g_off[b] = NN;
        }
    }
}

// ---------------- structure factors (kfilter folded in, f32x2 FMA) ----------
// R11 version — conflict-free e4*16B shared reads.
__global__ void __launch_bounds__(256, 4) sf_kernel() {
    int b  = blockIdx.z;
    int k0 = blockIdx.y * 32;
    int e0 = blockIdx.x * 32;
    int t = threadIdx.x;
    int e4 = t & 7;
    int ky = t >> 3;
    __shared__ float csh[32][32], ssh[32][32];
    __shared__ __align__(16) float hsh[32][32];
    int st = g_off[b], en = g_off[b + 1];
    uint64_t aR01 = 0, aR23 = 0, aI01 = 0, aI23 = 0;
    uint32_t hbase = smem_u32(&hsh[0][0]) + e4 * 16;
    for (int n0 = st; n0 < en; n0 += 32) {
#pragma unroll
        for (int l = 0; l < 4; l++) {
            int idx = t + 256 * l;
            int r = idx >> 5, c = idx & 31;
            int n = n0 + r;
            bool v = (n < en);
            csh[r][c] = v ? g_c[n * KK + k0 + c] : 0.f;
            ssh[r][c] = v ? g_s[n * KK + k0 + c] : 0.f;
            hsh[r][c] = v ? g_hres[(size_t)n * EE + e0 + c] : 0.f;
        }
        __syncthreads();
#pragma unroll
        for (int nn = 0; nn < 32; nn++) {
            uint64_t h01, h23, cv2, sv2;
            asm volatile("ld.shared.v2.u64 {%0, %1}, [%2];"
                         : "=l"(h01), "=l"(h23) : "r"(hbase + nn * 128));
            float cv = csh[nn][ky], sv = ssh[nn][ky];
            PACK2(cv2, cv);
            PACK2(sv2, sv);
            FMA2(aR01, cv2, h01);
            FMA2(aR23, cv2, h23);
            FMA2(aI01, sv2, h01);
            FMA2(aI23, sv2, h23);
        }
        __syncthreads();
    }
    float aR[4], aI[4];
    UNPACK2(aR[0], aR[1], aR01);
    UNPACK2(aR[2], aR[3], aR23);
    UNPACK2(aI[0], aI[1], aI01);
    UNPACK2(aI[2], aI[3], aI23);
    float4 f = *reinterpret_cast<float4*>(&g_kf[(k0 + ky) * EE + e0 + e4 * 4]);
    size_t idx = ((size_t)b * KK + k0 + ky) * EE + e0 + e4 * 4;
    float4 oR, oI;
    oR.x = aR[0] * f.x; oR.y = aR[1] * f.y; oR.z = aR[2] * f.z; oR.w = aR[3] * f.w;
    oI.x = aI[0] * f.x; oI.y = aI[1] * f.y; oI.z = aI[2] * f.z; oI.w = aI[3] * f.w;
    *reinterpret_cast<float4*>(&g_sfr[idx]) = oR;
    *reinterpret_cast<float4*>(&g_sfi[idx]) = oI;
}

// ---------------- back-projection (f32x2 FMA); writes hi/lo bf16 slabs ------
// R11 version.
__global__ void __launch_bounds__(256, 4) hupd_kernel(const int* __restrict__ seg) {
    int n0 = blockIdx.y * 32;
    int e0 = blockIdx.x * 32;
    int t = threadIdx.x;
    int e4 = t & 7;
    int ny = t >> 3;
    int n = n0 + ny;
    int b = seg[n];
    __shared__ float csh[32][32], ssh[32][32];
    uint64_t acc01 = 0, acc23 = 0;
    for (int k0c = 0; k0c < KK; k0c += 32) {
#pragma unroll
        for (int l = 0; l < 4; l++) {
            int idx = t + 256 * l;
            int r = idx >> 5, c = idx & 31;
            csh[r][c] = g_c[(n0 + r) * KK + k0c + c];
            ssh[r][c] = g_s[(n0 + r) * KK + k0c + c];
        }
        __syncthreads();
        const ulonglong2* baseR = reinterpret_cast<const ulonglong2*>(
            g_sfr + ((size_t)b * KK + k0c) * EE + e0 + e4 * 4);
        const ulonglong2* baseI = reinterpret_cast<const ulonglong2*>(
            g_sfi + ((size_t)b * KK + k0c) * EE + e0 + e4 * 4);
#pragma unroll
        for (int kk = 0; kk < 32; kk++) {
            float cv = csh[ny][kk];
            float sv = ssh[ny][kk];
            uint64_t cv2, sv2;
            PACK2(cv2, cv);
            PACK2(sv2, sv);
            ulonglong2 pr = baseR[(size_t)kk * (EE / 4)];
            ulonglong2 pi = baseI[(size_t)kk * (EE / 4)];
            FMA2(acc01, cv2, pr.x);
            FMA2(acc23, cv2, pr.y);
            FMA2(acc01, sv2, pi.x);
            FMA2(acc23, sv2, pi.y);
        }
        __syncthreads();
    }
    float acc[4];
    UNPACK2(acc[0], acc[1], acc01);
    UNPACK2(acc[2], acc[3], acc23);
    __nv_bfloat16 hi[4], lo[4];
#pragma unroll
    for (int q = 0; q < 4; q++) {
        float v = 0.01f * acc[q];
        hi[q] = __float2bfloat16(v);
        lo[q] = __float2bfloat16(v - __bfloat162float(hi[q]));
    }
    int e = e0 + e4 * 4;
    uint32_t loc = SWZ((uint32_t)(n * 128 + (e & 63) * 2));
    char* base = (char*)g_x2a;
    *reinterpret_cast<uint2*>(base + (size_t)(e >> 6) * ASLAB + loc) =
        *reinterpret_cast<uint2*>(hi);
    *reinterpret_cast<uint2*>(base + (size_t)(4 + (e >> 6)) * ASLAB + loc) =
        *reinterpret_cast<uint2*>(lo);
}

// ---------------- launch ----------------
extern "C" void kernel_launch(void* const* d_in, const int* in_sizes, int n_in,
                              void* d_out, int out_size) {
    const float *h = nullptr, *x = nullptr, *kv = nullptr;
    const float *Wpre = nullptr, *Wdn = nullptr, *Wup = nullptr;
    const float *W0 = nullptr, *Wres = nullptr;
    const int* seg = nullptr;

    for (int i = 0; i < n_in; i++) {
        switch (in_sizes[i]) {
            case NN * EE:           h    = (const float*)d_in[i]; break;
            case NN * 3:            x    = (const float*)d_in[i]; break;
            case BB * KK * 3:       kv   = (const float*)d_in[i]; break;
            case NN:                seg  = (const int*)d_in[i];   break;
            case 2 * EE * EE:       Wpre = (const float*)d_in[i]; break;
            case DD * KK:           Wdn  = (const float*)d_in[i]; break;
            case EE * DD:           Wup  = (const float*)d_in[i]; break;
            case EE * EE:           W0   = (const float*)d_in[i]; break;
            case 3 * 2 * EE * EE:   Wres = (const float*)d_in[i]; break;
            default: break;
        }
    }

    float* out = (float*)d_out;
    float* out_hu  = out;            // (NN, EE)
    float* out_dot = out + NN * EE;  // (NN, KK)

    float *t0, *hres;
    __nv_bfloat16 *x2a, *x2b, *wc;
    cudaGetSymbolAddress((void**)&t0,   g_t0);
    cudaGetSymbolAddress((void**)&hres, g_hres);
    cudaGetSymbolAddress((void**)&x2a,  g_x2a);
    cudaGetSymbolAddress((void**)&x2b,  g_x2b);
    cudaGetSymbolAddress((void**)&wc,   g_wc);

    cudaFuncSetAttribute(gemm_mma_kernel,
                         cudaFuncAttributeMaxDynamicSharedMemorySize, GEMM_SMEM);
    dim3 ggrid(EE / 64, NN / 64);  // (4, 64) = 256 CTAs -> 2/SM

    // fused conversions (conv_w + conv_h)
    conv_fused_kernel<<<6400, 256>>>(Wpre, W0, Wres, h);

    // fused geometry prep (dot + kf + seg offsets)
    prep_kernel<<<2192, 256>>>(x, kv, seg, Wup, Wdn, out_dot);

    // pre-residual: x2b = silu(h@W0'), hres = h + silu(x2b@W1')
    gemm_mma_kernel<<<ggrid, 256, GEMM_SMEM>>>(x2a, wc + 0 * 131072, nullptr, nullptr, x2b);
    gemm_mma_kernel<<<ggrid, 256, GEMM_SMEM>>>(x2b, wc + 1 * 131072, h, hres, nullptr);

    // structure factors + back-projection
    sf_kernel<<<dim3(EE / 32, KK / 32, BB), 256>>>();
    hupd_kernel<<<dim3(EE / 32, NN / 32), 256>>>(seg);  // -> g_x2a (slabbed hi/lo)

    // update MLP: t0 = silu(hu @ W0^T)
    gemm_mma_kernel<<<ggrid, 256, GEMM_SMEM>>>(x2a, wc + 2 * 131072, nullptr, t0, x2b);

    // 3 residual blocks
    for (int i = 0; i < 3; i++) {
        const __nv_bfloat16* wa = wc + (size_t)(3 + 2 * i) * 131072;
        const __nv_bfloat16* wb = wc + (size_t)(4 + 2 * i) * 131072;
        gemm_mma_kernel<<<ggrid, 256, GEMM_SMEM>>>(x2b, wa, nullptr, nullptr, x2a);
        float* dstf = (i == 2) ? out_hu : t0;
        __nv_bfloat16* dst2 = (i == 2) ? nullptr : x2b;
        gemm_mma_kernel<<<ggrid, 256, GEMM_SMEM>>>(x2a, wb, t0, dstf, dst2);
    }
}

// round 15
// speedup vs baseline: 1.2093x; 1.0102x over previous
#include <cuda_runtime.h>
#include <cuda_bf16.h>
#include <math.h>
#include <stdint.h>

// Problem constants (fixed shapes per reference)
#define NN 4096
#define EE 256
#define KK 128
#define BB 64
#define DD 8

// ---------------- scratch (no allocations allowed) ----------------
__device__ float g_t0[NN * EE];
__device__ float g_hres[NN * EE];
__device__ float g_c[NN * KK];
__device__ float g_s[NN * KK];
__device__ float g_sfr[BB * KK * EE];
__device__ float g_sfi[BB * KK * EE];
__device__ float g_kf[KK * EE];
__device__ int   g_off[BB + 1];
// Activations, SLAB layout: 8 slabs [c][4096 rows][64 bf16 = 128B], SW128-swizzled.
__device__ __align__(128) __nv_bfloat16 g_x2a[NN * 512];
__device__ __align__(128) __nv_bfloat16 g_x2b[NN * 512];
// Weights, SLAB layout: 9 gemms x [nblk 4][c 8][64 rows][64 bf16], swizzled.
__device__ __align__(128) __nv_bfloat16 g_wc[9 * 256 * 512];

// ---------------- helpers ----------------
__device__ __forceinline__ float silu(float v) {
    return v / (1.0f + __expf(-v));
}

__device__ __forceinline__ uint32_t smem_u32(const void* p) {
    uint32_t a;
    asm("{ .reg .u64 t; cvta.to.shared.u64 t, %1; cvt.u32.u64 %0, t; }" : "=r"(a) : "l"(p));
    return a;
}

#define SWZ(o) ((o) ^ (((o) >> 3) & 0x70))

#define LDMATRIX_X4(r0, r1, r2, r3, addr) \
    asm volatile("ldmatrix.sync.aligned.m8n8.x4.shared.b16 {%0,%1,%2,%3}, [%4];" \
                 : "=r"(r0), "=r"(r1), "=r"(r2), "=r"(r3) : "r"(addr))

#define MMA_BF16(c, a, b0, b1) \
    asm volatile("mma.sync.aligned.m16n8k16.row.col.f32.bf16.bf16.f32 " \
                 "{%0,%1,%2,%3},{%4,%5,%6,%7},{%8,%9},{%0,%1,%2,%3};" \
                 : "+f"((c)[0]), "+f"((c)[1]), "+f"((c)[2]), "+f"((c)[3]) \
                 : "r"((a)[0]), "r"((a)[1]), "r"((a)[2]), "r"((a)[3]), \
                   "r"(b0), "r"(b1))

#define MBAR_INIT(a, c) \
    asm volatile("mbarrier.init.shared.b64 [%0], %1;" :: "r"(a), "r"((uint32_t)(c)) : "memory")

#define MBAR_EXPECT_TX(a, n) \
    asm volatile("mbarrier.arrive.expect_tx.shared.b64 _, [%0], %1;" \
                 :: "r"(a), "r"((uint32_t)(n)) : "memory")

#define MBAR_WAIT(addr, ph) do { \
    uint32_t _m = (addr), _p = (uint32_t)(ph), _d; \
    asm volatile("{\n\t.reg .pred p;\n\tmbarrier.try_wait.parity.acquire.cta.shared::cta.b64 p, [%1], %2;\n\tselp.b32 %0, 1, 0, p;\n\t}" \
        : "=r"(_d) : "r"(_m), "r"(_p) : "memory"); \
    if (!_d) { \
        asm volatile("{\n\t.reg .pred P1;\n\tWL_%=:\n\tmbarrier.try_wait.parity.acquire.cta.shared::cta.b64 P1, [%0], %1, 0x989680;\n\t@P1 bra.uni WD_%=;\n\tbra.uni WL_%=;\n\tWD_%=:\n\t}" \
            :: "r"(_m), "r"(_p) : "memory"); \
    } \
} while (0)

#define CP_BULK(dst, src, bytes, mbar) \
    asm volatile("cp.async.bulk.shared::cta.global.mbarrier::complete_tx::bytes " \
                 "[%0], [%1], %2, [%3];" \
                 :: "r"(dst), "l"(src), "r"((uint32_t)(bytes)), "r"(mbar) : "memory")

// packed fp32x2 FMA helpers (SASS FFMA2 — PTX-only pattern)
#define PACK2(dst, v) \
    asm("mov.b64 %0, {%1, %1};" : "=l"(dst) : "f"(v))
#define FMA2(acc, a, b) \
    asm("fma.rn.f32x2 %0, %1, %2, %0;" : "+l"(acc) : "l"(a), "l"(b))
#define UNPACK2(lo, hi, v) \
    asm("mov.b64 {%0, %1}, %2;" : "=f"(lo), "=f"(hi) : "l"(v))

// ============================================================================
// HMMA GEMM, W-persistent, bulk-copy loads (R9/R11 config — best measured)
// ============================================================================
#define ASLAB (4096 * 128)
#define A_ST  8192
#define W_PB  65536
#define GEMM_SMEM (W_PB + 3 * A_ST)  // 90112 -> 2 CTAs/SM

__global__ void __launch_bounds__(256, 2) gemm_mma_kernel(
    const __nv_bfloat16* __restrict__ A2,
    const __nv_bfloat16* __restrict__ Wc,
    const float* __restrict__ skip,
    float* __restrict__ outf,
    __nv_bfloat16* __restrict__ out2)
{
    extern __shared__ char smem[];
    uint32_t sb = smem_u32(smem);
    __shared__ __align__(8) uint64_t mbars[4];

    int tid = threadIdx.x, wid = tid >> 5, lane = tid & 31;
    int m0 = blockIdx.y * 64, n0 = blockIdx.x * 64;
    int nb = blockIdx.x;
    int warp_m = (wid & 1) * 32, warp_n = (wid >> 1) * 16;

    uint32_t mb[3] = { smem_u32(&mbars[0]), smem_u32(&mbars[1]), smem_u32(&mbars[2]) };
    uint32_t wbar  = smem_u32(&mbars[3]);

    if (tid == 0) {
        MBAR_INIT(mb[0], 1);
        MBAR_INIT(mb[1], 1);
        MBAR_INIT(mb[2], 1);
        MBAR_INIT(wbar, 1);
    }
    __syncthreads();

    const char* gA = (const char*)A2 + (size_t)m0 * 128;
    const char* gW = (const char*)Wc + (size_t)nb * W_PB;

    if (tid == 0) {
        MBAR_EXPECT_TX(wbar, W_PB);
        CP_BULK(sb, gW, W_PB, wbar);
        MBAR_EXPECT_TX(mb[0], A_ST);
        CP_BULK(sb + W_PB, gA + 0 * (size_t)ASLAB, A_ST, mb[0]);
        MBAR_EXPECT_TX(mb[1], A_ST);
        CP_BULK(sb + W_PB + A_ST, gA + 1 * (size_t)ASLAB, A_ST, mb[1]);
    }

    float acc[2][2][4];
#pragma unroll
    for (int i = 0; i < 2; i++)
#pragma unroll
        for (int j = 0; j < 2; j++)
#pragma unroll
            for (int q = 0; q < 4; q++) acc[i][j][q] = 0.f;

    int arow0 = warp_m + (lane & 15);
    int brow  = warp_n + (lane & 15);
    int hi16  = (lane >> 4) * 16;

    MBAR_WAIT(wbar, 0);

#pragma unroll
    for (int ch = 0; ch < 8; ch++) {
        if (ch + 2 < 8 && tid == 0) {
            int ns = (ch + 2) % 3;
            MBAR_EXPECT_TX(mb[ns], A_ST);
            CP_BULK(sb + W_PB + ns * A_ST, gA + (size_t)(ch + 2) * ASLAB, A_ST, mb[ns]);
        }

        const int s = ch % 3;
        MBAR_WAIT(mb[s], (ch / 3) & 1);

        uint32_t aB = sb + W_PB + s * A_ST;
        const bool isHi = (ch < 4);
        const uint32_t whiB = sb + (uint32_t)((isHi ? ch : (ch - 4)) * 8192);
        const uint32_t wloB = sb + (uint32_t)((4 + ch) * 8192);

        uint32_t a[2][2][4], bh[2][4], bl[2][4];
        {
            uint32_t o0 = SWZ((uint32_t)(arow0 * 128 + hi16));
            uint32_t o1 = SWZ((uint32_t)((arow0 + 16) * 128 + hi16));
            LDMATRIX_X4(a[0][0][0], a[0][0][1], a[0][0][2], a[0][0][3], aB + o0);
            LDMATRIX_X4(a[0][1][0], a[0][1][1], a[0][1][2], a[0][1][3], aB + o1);
            uint32_t bo = SWZ((uint32_t)(brow * 128 + hi16));
            LDMATRIX_X4(bh[0][0], bh[0][1], bh[0][2], bh[0][3], whiB + bo);
            if (isHi) LDMATRIX_X4(bl[0][0], bl[0][1], bl[0][2], bl[0][3], wloB + bo);
        }

#pragma unroll
        for (int kh = 0; kh < 4; kh++) {
            const int cur = kh & 1, nxt = cur ^ 1;
            if (kh < 3) {
                uint32_t ko = (uint32_t)((kh + 1) * 32 + hi16);
                uint32_t o0 = SWZ((uint32_t)(arow0 * 128) + ko);
                uint32_t o1 = SWZ((uint32_t)((arow0 + 16) * 128) + ko);
                LDMATRIX_X4(a[nxt][0][0], a[nxt][0][1], a[nxt][0][2], a[nxt][0][3], aB + o0);
                LDMATRIX_X4(a[nxt][1][0], a[nxt][1][1], a[nxt][1][2], a[nxt][1][3], aB + o1);
                uint32_t bo = SWZ((uint32_t)(brow * 128) + ko);
                LDMATRIX_X4(bh[nxt][0], bh[nxt][1], bh[nxt][2], bh[nxt][3], whiB + bo);
                if (isHi) LDMATRIX_X4(bl[nxt][0], bl[nxt][1], bl[nxt][2], bl[nxt][3], wloB + bo);
            }
#pragma unroll
            for (int mt = 0; mt < 2; mt++)
#pragma unroll
                for (int j = 0; j < 2; j++)
                    MMA_BF16(acc[mt][j], a[cur][mt], bh[cur][j], bh[cur][j + 2]);
            if (isHi) {
#pragma unroll
                for (int mt = 0; mt < 2; mt++)
#pragma unroll
                    for (int j = 0; j < 2; j++)
                        MMA_BF16(acc[mt][j], a[cur][mt], bl[cur][j], bl[cur][j + 2]);
            }
        }

        __syncthreads();
    }

    // ---------------- epilogue ----------------
    char* o2 = (char*)out2;
    int r0 = lane >> 2, cp = (lane & 3) * 2;
#pragma unroll
    for (int mt = 0; mt < 2; mt++) {
#pragma unroll
        for (int j = 0; j < 2; j++) {
            int n = n0 + warp_n + j * 8 + cp;
#pragma unroll
            for (int half = 0; half < 2; half++) {
                int m = m0 + warp_m + mt * 16 + r0 + half * 8;
                float v0 = acc[mt][j][half * 2 + 0];
                float v1 = acc[mt][j][half * 2 + 1];
                v0 = silu(v0);
                v1 = silu(v1);
                if (skip) {
                    float2 sk = *reinterpret_cast<const float2*>(skip + (size_t)m * 256 + n);
                    v0 += sk.x; v1 += sk.y;
                }
                if (outf) {
                    float2 o; o.x = v0; o.y = v1;
                    *reinterpret_cast<float2*>(outf + (size_t)m * 256 + n) = o;
                }
                if (out2) {
                    __nv_bfloat16 h0 = __float2bfloat16(v0);
                    __nv_bfloat16 h1 = __float2bfloat16(v1);
                    __nv_bfloat162 hh; hh.x = h0; hh.y = h1;
                    __nv_bfloat162 ll;
                    ll.x = __float2bfloat16(v0 - __bfloat162float(h0));
                    ll.y = __float2bfloat16(v1 - __bfloat162float(h1));
                    uint32_t loc = SWZ((uint32_t)(m * 128 + (n & 63) * 2));
                    *reinterpret_cast<__nv_bfloat162*>(
                        o2 + (size_t)(n >> 6) * ASLAB + loc) = hh;
                    *reinterpret_cast<__nv_bfloat162*>(
                        o2 + (size_t)(4 + (n >> 6)) * ASLAB + loc) = ll;
                }
            }
        }
    }
}

// ============================================================================
// PRELUDE: all independent pre-GEMM work in ONE launch.
//   blocks [0, 2304)      conv_w  (9 gemms x 256 blocks)
//   blocks [2304, 6400)   conv_h  (4096 blocks)
//   blocks [6400, 8448)   dot     (2048 blocks, 2 atoms each)
//   blocks [8448, 8576)   kf      (128 blocks)
//   blocks [8576, 8592)   seg     (16 blocks)
// conv_* is HBM-bound; dot is MUFU-bound — co-scheduling overlaps them.
// ============================================================================
__global__ void prelude_kernel(const float* __restrict__ Wpre,
                               const float* __restrict__ W0,
                               const float* __restrict__ Wres,
                               const float* __restrict__ h,
                               const float* __restrict__ x,
                               const float* __restrict__ kvec,
                               const int* __restrict__ seg,
                               const float* __restrict__ Wup,
                               const float* __restrict__ Wdn,
                               float* __restrict__ dot_out) {
    int bid = blockIdx.x;
    int tid = threadIdx.x;
    if (bid < 2304) {
        int g = bid >> 8;
        int i = (bid & 255) * 256 + tid;
        int n = i >> 8, k = i & 255;
        const float* src = (g < 2) ? (Wpre + (size_t)g * 65536)
                         : (g == 2) ? W0
                         : (Wres + (size_t)(g - 3) * 65536);
        float v = src[i];
        __nv_bfloat16 hi = __float2bfloat16(v);
        __nv_bfloat16 lo = __float2bfloat16(v - __bfloat162float(hi));
        uint32_t loc = SWZ((uint32_t)((n & 63) * 128 + (k & 63) * 2));
        char* base = (char*)g_wc + (size_t)g * 262144 + (size_t)(n >> 6) * W_PB;
        *reinterpret_cast<__nv_bfloat16*>(base + (size_t)(k >> 6) * 8192 + loc) = hi;
        *reinterpret_cast<__nv_bfloat16*>(base + (size_t)(4 + (k >> 6)) * 8192 + loc) = lo;
    } else if (bid < 6400) {
        int idx = (bid - 2304) * 256 + tid;
        int m = idx >> 8, e = idx & 255;
        float v = h[idx];
        __nv_bfloat16 hi = __float2bfloat16(v);
        __nv_bfloat16 lo = __float2bfloat16(v - __bfloat162float(hi));
        uint32_t loc = SWZ((uint32_t)(m * 128 + (e & 63) * 2));
        char* base = (char*)g_x2a;
        *reinterpret_cast<__nv_bfloat16*>(base + (size_t)(e >> 6) * ASLAB + loc) = hi;
        *reinterpret_cast<__nv_bfloat16*>(base + (size_t)(4 + (e >> 6)) * ASLAB + loc) = lo;
    } else if (bid < 8448) {
        int n = (bid - 6400) * 2 + (tid >> 7);
        int kk = tid & 127;
        int b = seg[n];
        float x0 = x[n * 3 + 0], x1 = x[n * 3 + 1], x2 = x[n * 3 + 2];
        const float* kr = kvec + ((size_t)b * KK + kk) * 3;
        float d = kr[0] * x0 + kr[1] * x1 + kr[2] * x2;
        dot_out[n * KK + kk] = d;
        float cv, sv;
        sincosf(d, &sv, &cv);
        g_c[n * KK + kk] = cv;
        g_s[n * KK + kk] = sv;
    } else if (bid < 8576) {
        int k = bid - 8448;
        int e = tid;
        float a = 0.f;
#pragma unroll
        for (int d = 0; d < DD; d++) a += Wup[e * DD + d] * Wdn[d * KK + k];
        g_kf[k * EE + e] = a;
    } else {
        int n = (bid - 8576) * 256 + tid;
        int s = seg[n];
        if (n == 0) {
            for (int b = 0; b <= s; b++) g_off[b] = 0;
        } else {
            int p = seg[n - 1];
            for (int b = p + 1; b <= s; b++) g_off[b] = n;
        }
        if (n == NN - 1) {
            for (int b = s + 1; b <= BB; b++) g_off[b] = NN;
        }
    }
}

// ---------------- structure factors (kfilter folded in, f32x2 FMA) ----------
__global__ void __launch_bounds__(256, 4) sf_kernel() {
    int b  = blockIdx.z;
    int k0 = blockIdx.y * 32;
    int e0 = blockIdx.x * 32;
    int t = threadIdx.x;
    int e4 = t & 7;
    int ky = t >> 3;
    __shared__ float csh[32][32], ssh[32][32];
    __shared__ __align__(16) float hsh[32][32];
    int st = g_off[b], en = g_off[b + 1];
    uint64_t aR01 = 0, aR23 = 0, aI01 = 0, aI23 = 0;
    uint32_t hbase = smem_u32(&hsh[0][0]) + e4 * 16;
    for (int n0 = st; n0 < en; n0 += 32) {
#pragma unroll
        for (int l = 0; l < 4; l++) {
            int idx = t + 256 * l;
            int r = idx >> 5, c = idx & 31;
            int n = n0 + r;
            bool v = (n < en);
            csh[r][c] = v ? g_c[n * KK + k0 + c] : 0.f;
            ssh[r][c] = v ? g_s[n * KK + k0 + c] : 0.f;
            hsh[r][c] = v ? g_hres[(size_t)n * EE + e0 + c] : 0.f;
        }
        __syncthreads();
#pragma unroll
        for (int nn = 0; nn < 32; nn++) {
            uint64_t h01, h23, cv2, sv2;
            asm volatile("ld.shared.v2.u64 {%0, %1}, [%2];"
                         : "=l"(h01), "=l"(h23) : "r"(hbase + nn * 128));
            float cv = csh[nn][ky], sv = ssh[nn][ky];
            PACK2(cv2, cv);
            PACK2(sv2, sv);
            FMA2(aR01, cv2, h01);
            FMA2(aR23, cv2, h23);
            FMA2(aI01, sv2, h01);
            FMA2(aI23, sv2, h23);
        }
        __syncthreads();
    }
    float aR[4], aI[4];
    UNPACK2(aR[0], aR[1], aR01);
    UNPACK2(aR[2], aR[3], aR23);
    UNPACK2(aI[0], aI[1], aI01);
    UNPACK2(aI[2], aI[3], aI23);
    float4 f = *reinterpret_cast<float4*>(&g_kf[(k0 + ky) * EE + e0 + e4 * 4]);
    size_t idx = ((size_t)b * KK + k0 + ky) * EE + e0 + e4 * 4;
    float4 oR, oI;
    oR.x = aR[0] * f.x; oR.y = aR[1] * f.y; oR.z = aR[2] * f.z; oR.w = aR[3] * f.w;
    oI.x = aI[0] * f.x; oI.y = aI[1] * f.y; oI.z = aI[2] * f.z; oI.w = aI[3] * f.w;
    *reinterpret_cast<float4*>(&g_sfr[idx]) = oR;
    *reinterpret_cast<float4*>(&g_sfi[idx]) = oI;
}

// ---------------- back-projection (f32x2 FMA); writes hi/lo bf16 slabs ------
__global__ void __launch_bounds__(256, 4) hupd_kernel(const int* __restrict__ seg) {
    int n0 = blockIdx.y * 32;
    int e0 = blockIdx.x * 32;
    int t = threadIdx.x;
    int e4 = t & 7;
    int ny = t >> 3;
    int n = n0 + ny;
    int b = seg[n];
    __shared__ float csh[32][32], ssh[32][32];
    uint64_t acc01 = 0, acc23 = 0;
    for (int k0c = 0; k0c < KK; k0c += 32) {
#pragma unroll
        for (int l = 0; l < 4; l++) {
            int idx = t + 256 * l;
            int r = idx >> 5, c = idx & 31;
            csh[r][c] = g_c[(n0 + r) * KK + k0c + c];
            ssh[r][c] = g_s[(n0 + r) * KK + k0c + c];
        }
        __syncthreads();
        const ulonglong2* baseR = reinterpret_cast<const ulonglong2*>(
            g_sfr + ((size_t)b * KK + k0c) * EE + e0 + e4 * 4);
        const ulonglong2* baseI = reinterpret_cast<const ulonglong2*>(
            g_sfi + ((size_t)b * KK + k0c) * EE + e0 + e4 * 4);
#pragma unroll
        for (int kk = 0; kk < 32; kk++) {
            float cv = csh[ny][kk];
            float sv = ssh[ny][kk];
            uint64_t cv2, sv2;
            PACK2(cv2, cv);
            PACK2(sv2, sv);
            ulonglong2 pr = baseR[(size_t)kk * (EE / 4)];
            ulonglong2 pi = baseI[(size_t)kk * (EE / 4)];
            FMA2(acc01, cv2, pr.x);
            FMA2(acc23, cv2, pr.y);
            FMA2(acc01, sv2, pi.x);
            FMA2(acc23, sv2, pi.y);
        }
        __syncthreads();
    }
    float acc[4];
    UNPACK2(acc[0], acc[1], acc01);
    UNPACK2(acc[2], acc[3], acc23);
    __nv_bfloat16 hi[4], lo[4];
#pragma unroll
    for (int q = 0; q < 4; q++) {
        float v = 0.01f * acc[q];
        hi[q] = __float2bfloat16(v);
        lo[q] = __float2bfloat16(v - __bfloat162float(hi[q]));
    }
    int e = e0 + e4 * 4;
    uint32_t loc = SWZ((uint32_t)(n * 128 + (e & 63) * 2));
    char* base = (char*)g_x2a;
    *reinterpret_cast<uint2*>(base + (size_t)(e >> 6) * ASLAB + loc) =
        *reinterpret_cast<uint2*>(hi);
    *reinterpret_cast<uint2*>(base + (size_t)(4 + (e >> 6)) * ASLAB + loc) =
        *reinterpret_cast<uint2*>(lo);
}

// ---------------- launch ----------------
extern "C" void kernel_launch(void* const* d_in, const int* in_sizes, int n_in,
                              void* d_out, int out_size) {
    const float *h = nullptr, *x = nullptr, *kv = nullptr;
    const float *Wpre = nullptr, *Wdn = nullptr, *Wup = nullptr;
    const float *W0 = nullptr, *Wres = nullptr;
    const int* seg = nullptr;

    for (int i = 0; i < n_in; i++) {
        switch (in_sizes[i]) {
            case NN * EE:           h    = (const float*)d_in[i]; break;
            case NN * 3:            x    = (const float*)d_in[i]; break;
            case BB * KK * 3:       kv   = (const float*)d_in[i]; break;
            case NN:                seg  = (const int*)d_in[i];   break;
            case 2 * EE * EE:       Wpre = (const float*)d_in[i]; break;
            case DD * KK:           Wdn  = (const float*)d_in[i]; break;
            case EE * DD:           Wup  = (const float*)d_in[i]; break;
            case EE * EE:           W0   = (const float*)d_in[i]; break;
            case 3 * 2 * EE * EE:   Wres = (const float*)d_in[i]; break;
            default: break;
        }
    }

    float* out = (float*)d_out;
    float* out_hu  = out;            // (NN, EE)
    float* out_dot = out + NN * EE;  // (NN, KK)

    float *t0, *hres;
    __nv_bfloat16 *x2a, *x2b, *wc;
    cudaGetSymbolAddress((void**)&t0,   g_t0);
    cudaGetSymbolAddress((void**)&hres, g_hres);
    cudaGetSymbolAddress((void**)&x2a,  g_x2a);
    cudaGetSymbolAddress((void**)&x2b,  g_x2b);
    cudaGetSymbolAddress((void**)&wc,   g_wc);

    cudaFuncSetAttribute(gemm_mma_kernel,
                         cudaFuncAttributeMaxDynamicSharedMemorySize, GEMM_SMEM);
    dim3 ggrid(EE / 64, NN / 64);  // (4, 64) = 256 CTAs -> 2/SM

    // all independent pre-GEMM work in one launch
    prelude_kernel<<<8592, 256>>>(Wpre, W0, Wres, h, x, kv, seg, Wup, Wdn, out_dot);

    // pre-residual: x2b = silu(h@W0'), hres = h + silu(x2b@W1')
    gemm_mma_kernel<<<ggrid, 256, GEMM_SMEM>>>(x2a, wc + 0 * 131072, nullptr, nullptr, x2b);
    gemm_mma_kernel<<<ggrid, 256, GEMM_SMEM>>>(x2b, wc + 1 * 131072, h, hres, nullptr);

    // structure factors + back-projection
    sf_kernel<<<dim3(EE / 32, KK / 32, BB), 256>>>();
    hupd_kernel<<<dim3(EE / 32, NN / 32), 256>>>(seg);  // -> g_x2a (slabbed hi/lo)

    // update MLP: t0 = silu(hu @ W0^T)
    gemm_mma_kernel<<<ggrid, 256, GEMM_SMEM>>>(x2a, wc + 2 * 131072, nullptr, t0, x2b);

    // 3 residual blocks
    for (int i = 0; i < 3; i++) {
        const __nv_bfloat16* wa = wc + (size_t)(3 + 2 * i) * 131072;
        const __nv_bfloat16* wb = wc + (size_t)(4 + 2 * i) * 131072;
        gemm_mma_kernel<<<ggrid, 256, GEMM_SMEM>>>(x2b, wa, nullptr, nullptr, x2a);
        float* dstf = (i == 2) ? out_hu : t0;
        __nv_bfloat16* dst2 = (i == 2) ? nullptr : x2b;
        gemm_mma_kernel<<<ggrid, 256, GEMM_SMEM>>>(x2a, wb, t0, dstf, dst2);
    }
}

// round 16
// speedup vs baseline: 1.2910x; 1.0676x over previous
#include <cuda_runtime.h>
#include <cuda_bf16.h>
#include <math.h>
#include <stdint.h>

// Problem constants (fixed shapes per reference)
#define NN 4096
#define EE 256
#define KK 128
#define BB 64
#define DD 8

// ---------------- scratch (no allocations allowed) ----------------
__device__ float g_t0[NN * EE];
__device__ float g_hres[NN * EE];
__device__ float g_c[NN * KK];
__device__ float g_s[NN * KK];
__device__ float g_sfr[BB * KK * EE];
__device__ float g_sfi[BB * KK * EE];
__device__ float g_kf[KK * EE];
__device__ int   g_off[BB + 1];
// Activations, SLAB layout: 8 slabs [c][4096 rows][64 bf16 = 128B], SW128-swizzled.
__device__ __align__(128) __nv_bfloat16 g_x2a[NN * 512];
__device__ __align__(128) __nv_bfloat16 g_x2b[NN * 512];
// Weights, SLAB layout: 9 gemms x [nblk 4][c 8][64 rows][64 bf16], swizzled.
__device__ __align__(128) __nv_bfloat16 g_wc[9 * 256 * 512];

// ---------------- helpers ----------------
__device__ __forceinline__ float silu(float v) {
    return v / (1.0f + __expf(-v));
}

__device__ __forceinline__ uint32_t smem_u32(const void* p) {
    uint32_t a;
    asm("{ .reg .u64 t; cvta.to.shared.u64 t, %1; cvt.u32.u64 %0, t; }" : "=r"(a) : "l"(p));
    return a;
}

#define SWZ(o) ((o) ^ (((o) >> 3) & 0x70))

#define LDMATRIX_X4(r0, r1, r2, r3, addr) \
    asm volatile("ldmatrix.sync.aligned.m8n8.x4.shared.b16 {%0,%1,%2,%3}, [%4];" \
                 : "=r"(r0), "=r"(r1), "=r"(r2), "=r"(r3) : "r"(addr))

#define MMA_BF16(c, a, b0, b1) \
    asm volatile("mma.sync.aligned.m16n8k16.row.col.f32.bf16.bf16.f32 " \
                 "{%0,%1,%2,%3},{%4,%5,%6,%7},{%8,%9},{%0,%1,%2,%3};" \
                 : "+f"((c)[0]), "+f"((c)[1]), "+f"((c)[2]), "+f"((c)[3]) \
                 : "r"((a)[0]), "r"((a)[1]), "r"((a)[2]), "r"((a)[3]), \
                   "r"(b0), "r"(b1))

#define MBAR_INIT(a, c) \
    asm volatile("mbarrier.init.shared.b64 [%0], %1;" :: "r"(a), "r"((uint32_t)(c)) : "memory")

#define MBAR_EXPECT_TX(a, n) \
    asm volatile("mbarrier.arrive.expect_tx.shared.b64 _, [%0], %1;" \
                 :: "r"(a), "r"((uint32_t)(n)) : "memory")

#define MBAR_WAIT(addr, ph) do { \
    uint32_t _m = (addr), _p = (uint32_t)(ph), _d; \
    asm volatile("{\n\t.reg .pred p;\n\tmbarrier.try_wait.parity.acquire.cta.shared::cta.b64 p, [%1], %2;\n\tselp.b32 %0, 1, 0, p;\n\t}" \
        : "=r"(_d) : "r"(_m), "r"(_p) : "memory"); \
    if (!_d) { \
        asm volatile("{\n\t.reg .pred P1;\n\tWL_%=:\n\tmbarrier.try_wait.parity.acquire.cta.shared::cta.b64 P1, [%0], %1, 0x989680;\n\t@P1 bra.uni WD_%=;\n\tbra.uni WL_%=;\n\tWD_%=:\n\t}" \
            :: "r"(_m), "r"(_p) : "memory"); \
    } \
} while (0)

#define CP_BULK(dst, src, bytes, mbar) \
    asm volatile("cp.async.bulk.shared::cta.global.mbarrier::complete_tx::bytes " \
                 "[%0], [%1], %2, [%3];" \
                 :: "r"(dst), "l"(src), "r"((uint32_t)(bytes)), "r"(mbar) : "memory")

// packed fp32x2 FMA helpers (SASS FFMA2 — PTX-only pattern)
#define PACK2(dst, v) \
    asm("mov.b64 %0, {%1, %1};" : "=l"(dst) : "f"(v))
#define FMA2(acc, a, b) \
    asm("fma.rn.f32x2 %0, %1, %2, %0;" : "+l"(acc) : "l"(a), "l"(b))
#define UNPACK2(lo, hi, v) \
    asm("mov.b64 {%0, %1}, %2;" : "=f"(lo), "=f"(hi) : "l"(v))

// ============================================================================
// HMMA GEMM, W-persistent, bulk-copy loads (R9/R11 config — best measured)
// ============================================================================
#define ASLAB (4096 * 128)
#define A_ST  8192
#define W_PB  65536
#define GEMM_SMEM (W_PB + 3 * A_ST)  // 90112 -> 2 CTAs/SM

__global__ void __launch_bounds__(256, 2) gemm_mma_kernel(
    const __nv_bfloat16* __restrict__ A2,
    const __nv_bfloat16* __restrict__ Wc,
    const float* __restrict__ skip,
    float* __restrict__ outf,
    __nv_bfloat16* __restrict__ out2)
{
    extern __shared__ char smem[];
    uint32_t sb = smem_u32(smem);
    __shared__ __align__(8) uint64_t mbars[4];

    int tid = threadIdx.x, wid = tid >> 5, lane = tid & 31;
    int m0 = blockIdx.y * 64, n0 = blockIdx.x * 64;
    int nb = blockIdx.x;
    int warp_m = (wid & 1) * 32, warp_n = (wid >> 1) * 16;

    uint32_t mb[3] = { smem_u32(&mbars[0]), smem_u32(&mbars[1]), smem_u32(&mbars[2]) };
    uint32_t wbar  = smem_u32(&mbars[3]);

    if (tid == 0) {
        MBAR_INIT(mb[0], 1);
        MBAR_INIT(mb[1], 1);
        MBAR_INIT(mb[2], 1);
        MBAR_INIT(wbar, 1);
    }
    __syncthreads();

    const char* gA = (const char*)A2 + (size_t)m0 * 128;
    const char* gW = (const char*)Wc + (size_t)nb * W_PB;

    if (tid == 0) {
        MBAR_EXPECT_TX(wbar, W_PB);
        CP_BULK(sb, gW, W_PB, wbar);
        MBAR_EXPECT_TX(mb[0], A_ST);
        CP_BULK(sb + W_PB, gA + 0 * (size_t)ASLAB, A_ST, mb[0]);
        MBAR_EXPECT_TX(mb[1], A_ST);
        CP_BULK(sb + W_PB + A_ST, gA + 1 * (size_t)ASLAB, A_ST, mb[1]);
    }

    float acc[2][2][4];
#pragma unroll
    for (int i = 0; i < 2; i++)
#pragma unroll
        for (int j = 0; j < 2; j++)
#pragma unroll
            for (int q = 0; q < 4; q++) acc[i][j][q] = 0.f;

    int arow0 = warp_m + (lane & 15);
    int brow  = warp_n + (lane & 15);
    int hi16  = (lane >> 4) * 16;

    MBAR_WAIT(wbar, 0);

#pragma unroll
    for (int ch = 0; ch < 8; ch++) {
        if (ch + 2 < 8 && tid == 0) {
            int ns = (ch + 2) % 3;
            MBAR_EXPECT_TX(mb[ns], A_ST);
            CP_BULK(sb + W_PB + ns * A_ST, gA + (size_t)(ch + 2) * ASLAB, A_ST, mb[ns]);
        }

        const int s = ch % 3;
        MBAR_WAIT(mb[s], (ch / 3) & 1);

        uint32_t aB = sb + W_PB + s * A_ST;
        const bool isHi = (ch < 4);
        const uint32_t whiB = sb + (uint32_t)((isHi ? ch : (ch - 4)) * 8192);
        const uint32_t wloB = sb + (uint32_t)((4 + ch) * 8192);

        uint32_t a[2][2][4], bh[2][4], bl[2][4];
        {
            uint32_t o0 = SWZ((uint32_t)(arow0 * 128 + hi16));
            uint32_t o1 = SWZ((uint32_t)((arow0 + 16) * 128 + hi16));
            LDMATRIX_X4(a[0][0][0], a[0][0][1], a[0][0][2], a[0][0][3], aB + o0);
            LDMATRIX_X4(a[0][1][0], a[0][1][1], a[0][1][2], a[0][1][3], aB + o1);
            uint32_t bo = SWZ((uint32_t)(brow * 128 + hi16));
            LDMATRIX_X4(bh[0][0], bh[0][1], bh[0][2], bh[0][3], whiB + bo);
            if (isHi) LDMATRIX_X4(bl[0][0], bl[0][1], bl[0][2], bl[0][3], wloB + bo);
        }

#pragma unroll
        for (int kh = 0; kh < 4; kh++) {
            const int cur = kh & 1, nxt = cur ^ 1;
            if (kh < 3) {
                uint32_t ko = (uint32_t)((kh + 1) * 32 + hi16);
                uint32_t o0 = SWZ((uint32_t)(arow0 * 128) + ko);
                uint32_t o1 = SWZ((uint32_t)((arow0 + 16) * 128) + ko);
                LDMATRIX_X4(a[nxt][0][0], a[nxt][0][1], a[nxt][0][2], a[nxt][0][3], aB + o0);
                LDMATRIX_X4(a[nxt][1][0], a[nxt][1][1], a[nxt][1][2], a[nxt][1][3], aB + o1);
                uint32_t bo = SWZ((uint32_t)(brow * 128) + ko);
                LDMATRIX_X4(bh[nxt][0], bh[nxt][1], bh[nxt][2], bh[nxt][3], whiB + bo);
                if (isHi) LDMATRIX_X4(bl[nxt][0], bl[nxt][1], bl[nxt][2], bl[nxt][3], wloB + bo);
            }
#pragma unroll
            for (int mt = 0; mt < 2; mt++)
#pragma unroll
                for (int j = 0; j < 2; j++)
                    MMA_BF16(acc[mt][j], a[cur][mt], bh[cur][j], bh[cur][j + 2]);
            if (isHi) {
#pragma unroll
                for (int mt = 0; mt < 2; mt++)
#pragma unroll
                    for (int j = 0; j < 2; j++)
                        MMA_BF16(acc[mt][j], a[cur][mt], bl[cur][j], bl[cur][j + 2]);
            }
        }

        __syncthreads();
    }

    // ---------------- epilogue ----------------
    char* o2 = (char*)out2;
    int r0 = lane >> 2, cp = (lane & 3) * 2;
#pragma unroll
    for (int mt = 0; mt < 2; mt++) {
#pragma unroll
        for (int j = 0; j < 2; j++) {
            int n = n0 + warp_n + j * 8 + cp;
#pragma unroll
            for (int half = 0; half < 2; half++) {
                int m = m0 + warp_m + mt * 16 + r0 + half * 8;
                float v0 = acc[mt][j][half * 2 + 0];
                float v1 = acc[mt][j][half * 2 + 1];
                v0 = silu(v0);
                v1 = silu(v1);
                if (skip) {
                    float2 sk = *reinterpret_cast<const float2*>(skip + (size_t)m * 256 + n);
                    v0 += sk.x; v1 += sk.y;
                }
                if (outf) {
                    float2 o; o.x = v0; o.y = v1;
                    *reinterpret_cast<float2*>(outf + (size_t)m * 256 + n) = o;
                }
                if (out2) {
                    __nv_bfloat16 h0 = __float2bfloat16(v0);
                    __nv_bfloat16 h1 = __float2bfloat16(v1);
                    __nv_bfloat162 hh; hh.x = h0; hh.y = h1;
                    __nv_bfloat162 ll;
                    ll.x = __float2bfloat16(v0 - __bfloat162float(h0));
                    ll.y = __float2bfloat16(v1 - __bfloat162float(h1));
                    uint32_t loc = SWZ((uint32_t)(m * 128 + (n & 63) * 2));
                    *reinterpret_cast<__nv_bfloat162*>(
                        o2 + (size_t)(n >> 6) * ASLAB + loc) = hh;
                    *reinterpret_cast<__nv_bfloat162*>(
                        o2 + (size_t)(4 + (n >> 6)) * ASLAB + loc) = ll;
                }
            }
        }
    }
}

// ============================================================================
// PRELUDE: all independent pre-GEMM work in ONE launch (validated R15 win).
// ============================================================================
__global__ void prelude_kernel(const float* __restrict__ Wpre,
                               const float* __restrict__ W0,
                               const float* __restrict__ Wres,
                               const float* __restrict__ h,
                               const float* __restrict__ x,
                               const float* __restrict__ kvec,
                               const int* __restrict__ seg,
                               const float* __restrict__ Wup,
                               const float* __restrict__ Wdn,
                               float* __restrict__ dot_out) {
    int bid = blockIdx.x;
    int tid = threadIdx.x;
    if (bid < 2304) {
        int g = bid >> 8;
        int i = (bid & 255) * 256 + tid;
        int n = i >> 8, k = i & 255;
        const float* src = (g < 2) ? (Wpre + (size_t)g * 65536)
                         : (g == 2) ? W0
                         : (Wres + (size_t)(g - 3) * 65536);
        float v = src[i];
        __nv_bfloat16 hi = __float2bfloat16(v);
        __nv_bfloat16 lo = __float2bfloat16(v - __bfloat162float(hi));
        uint32_t loc = SWZ((uint32_t)((n & 63) * 128 + (k & 63) * 2));
        char* base = (char*)g_wc + (size_t)g * 262144 + (size_t)(n >> 6) * W_PB;
        *reinterpret_cast<__nv_bfloat16*>(base + (size_t)(k >> 6) * 8192 + loc) = hi;
        *reinterpret_cast<__nv_bfloat16*>(base + (size_t)(4 + (k >> 6)) * 8192 + loc) = lo;
    } else if (bid < 6400) {
        int idx = (bid - 2304) * 256 + tid;
        int m = idx >> 8, e = idx & 255;
        float v = h[idx];
        __nv_bfloat16 hi = __float2bfloat16(v);
        __nv_bfloat16 lo = __float2bfloat16(v - __bfloat162float(hi));
        uint32_t loc = SWZ((uint32_t)(m * 128 + (e & 63) * 2));
        char* base = (char*)g_x2a;
        *reinterpret_cast<__nv_bfloat16*>(base + (size_t)(e >> 6) * ASLAB + loc) = hi;
        *reinterpret_cast<__nv_bfloat16*>(base + (size_t)(4 + (e >> 6)) * ASLAB + loc) = lo;
    } else if (bid < 8448) {
        int n = (bid - 6400) * 2 + (tid >> 7);
        int kk = tid & 127;
        int b = seg[n];
        float x0 = x[n * 3 + 0], x1 = x[n * 3 + 1], x2 = x[n * 3 + 2];
        const float* kr = kvec + ((size_t)b * KK + kk) * 3;
        float d = kr[0] * x0 + kr[1] * x1 + kr[2] * x2;
        dot_out[n * KK + kk] = d;
        float cv, sv;
        sincosf(d, &sv, &cv);
        g_c[n * KK + kk] = cv;
        g_s[n * KK + kk] = sv;
    } else if (bid < 8576) {
        int k = bid - 8448;
        int e = tid;
        float a = 0.f;
#pragma unroll
        for (int d = 0; d < DD; d++) a += Wup[e * DD + d] * Wdn[d * KK + k];
        g_kf[k * EE + e] = a;
    } else {
        int n = (bid - 8576) * 256 + tid;
        int s = seg[n];
        if (n == 0) {
            for (int b = 0; b <= s; b++) g_off[b] = 0;
        } else {
            int p = seg[n - 1];
            for (int b = p + 1; b <= s; b++) g_off[b] = n;
        }
        if (n == NN - 1) {
            for (int b = s + 1; b <= BB; b++) g_off[b] = NN;
        }
    }
}

// ---------------- structure factors v3: tile k64 x e32, thread k2 x e4 ------
// LDS bytes per FMA2: 6 -> 4. k is widened (keeps conflict-free e4*16B h reads
// AND 8B-pair c/s reads). k-blocks halve: global h reloads through L1 halve.
__global__ void __launch_bounds__(256, 3) sf_kernel() {
    int b  = blockIdx.z;
    int k0 = blockIdx.y * 64;
    int e0 = blockIdx.x * 32;
    int t = threadIdx.x;
    int e4 = t & 7;     // e = e0 + e4*4 .. +4
    int ky = t >> 3;    // k pair: k = k0 + ky*2 + {0,1}
    __shared__ __align__(8)  float csh[32][64], ssh[32][64];
    __shared__ __align__(16) float hsh[32][32];
    int st = g_off[b], en = g_off[b + 1];

    // acc[k-in-pair][R/I][e-pair] as uint64 f32x2
    uint64_t aR0[2] = {0, 0}, aR1[2] = {0, 0};
    uint64_t aI0[2] = {0, 0}, aI1[2] = {0, 0};

    uint32_t hbase = smem_u32(&hsh[0][0]) + e4 * 16;
    uint32_t cbase = smem_u32(&csh[0][0]) + ky * 8;
    uint32_t sbase = smem_u32(&ssh[0][0]) + ky * 8;

    for (int n0 = st; n0 < en; n0 += 32) {
#pragma unroll
        for (int l = 0; l < 8; l++) {
            int idx = t + 256 * l;
            int r = idx >> 6, c = idx & 63;
            int n = n0 + r;
            bool v = (n < en);
            csh[r][c] = v ? g_c[n * KK + k0 + c] : 0.f;
            ssh[r][c] = v ? g_s[n * KK + k0 + c] : 0.f;
        }
#pragma unroll
        for (int l = 0; l < 4; l++) {
            int idx = t + 256 * l;
            int r = idx >> 5, c = idx & 31;
            int n = n0 + r;
            hsh[r][c] = (n < en) ? g_hres[(size_t)n * EE + e0 + c] : 0.f;
        }
        __syncthreads();
#pragma unroll
        for (int nn = 0; nn < 32; nn++) {
            uint64_t h01, h23;
            asm volatile("ld.shared.v2.u64 {%0, %1}, [%2];"
                         : "=l"(h01), "=l"(h23) : "r"(hbase + nn * 128));
            float c0, c1, s0, s1;
            asm volatile("ld.shared.v2.f32 {%0, %1}, [%2];"
                         : "=f"(c0), "=f"(c1) : "r"(cbase + nn * 256));
            asm volatile("ld.shared.v2.f32 {%0, %1}, [%2];"
                         : "=f"(s0), "=f"(s1) : "r"(sbase + nn * 256));
            uint64_t c02, c12, s02, s12;
            PACK2(c02, c0); PACK2(c12, c1); PACK2(s02, s0); PACK2(s12, s1);
            FMA2(aR0[0], c02, h01); FMA2(aR0[1], c02, h23);
            FMA2(aR1[0], c12, h01); FMA2(aR1[1], c12, h23);
            FMA2(aI0[0], s02, h01); FMA2(aI0[1], s02, h23);
            FMA2(aI1[0], s12, h01); FMA2(aI1[1], s12, h23);
        }
        __syncthreads();
    }

    // epilogue: 2 k rows x 4 e each, kfilter folded in
#pragma unroll
    for (int kk = 0; kk < 2; kk++) {
        int k = k0 + ky * 2 + kk;
        float aR[4], aI[4];
        if (kk == 0) {
            UNPACK2(aR[0], aR[1], aR0[0]); UNPACK2(aR[2], aR[3], aR0[1]);
            UNPACK2(aI[0], aI[1], aI0[0]); UNPACK2(aI[2], aI[3], aI0[1]);
        } else {
            UNPACK2(aR[0], aR[1], aR1[0]); UNPACK2(aR[2], aR[3], aR1[1]);
            UNPACK2(aI[0], aI[1], aI1[0]); UNPACK2(aI[2], aI[3], aI1[1]);
        }
        float4 f = *reinterpret_cast<const float4*>(&g_kf[(size_t)k * EE + e0 + e4 * 4]);
        size_t idx = ((size_t)b * KK + k) * EE + e0 + e4 * 4;
        float4 oR, oI;
        oR.x = aR[0] * f.x; oR.y = aR[1] * f.y; oR.z = aR[2] * f.z; oR.w = aR[3] * f.w;
        oI.x = aI[0] * f.x; oI.y = aI[1] * f.y; oI.z = aI[2] * f.z; oI.w = aI[3] * f.w;
        *reinterpret_cast<float4*>(&g_sfr[idx]) = oR;
        *reinterpret_cast<float4*>(&g_sfi[idx]) = oI;
    }
}

// ---------------- back-projection (f32x2 FMA); writes hi/lo bf16 slabs ------
// R11 version (proven).
__global__ void __launch_bounds__(256, 4) hupd_kernel(const int* __restrict__ seg) {
    int n0 = blockIdx.y * 32;
    int e0 = blockIdx.x * 32;
    int t = threadIdx.x;
    int e4 = t & 7;
    int ny = t >> 3;
    int n = n0 + ny;
    int b = seg[n];
    __shared__ float csh[32][32], ssh[32][32];
    uint64_t acc01 = 0, acc23 = 0;
    for (int k0c = 0; k0c < KK; k0c += 32) {
#pragma unroll
        for (int l = 0; l < 4; l++) {
            int idx = t + 256 * l;
            int r = idx >> 5, c = idx & 31;
            csh[r][c] = g_c[(n0 + r) * KK + k0c + c];
            ssh[r][c] = g_s[(n0 + r) * KK + k0c + c];
        }
        __syncthreads();
        const ulonglong2* baseR = reinterpret_cast<const ulonglong2*>(
            g_sfr + ((size_t)b * KK + k0c) * EE + e0 + e4 * 4);
        const ulonglong2* baseI = reinterpret_cast<const ulonglong2*>(
            g_sfi + ((size_t)b * KK + k0c) * EE + e0 + e4 * 4);
#pragma unroll
        for (int kk = 0; kk < 32; kk++) {
            float cv = csh[ny][kk];
            float sv = ssh[ny][kk];
            uint64_t cv2, sv2;
            PACK2(cv2, cv);
            PACK2(sv2, sv);
            ulonglong2 pr = baseR[(size_t)kk * (EE / 4)];
            ulonglong2 pi = baseI[(size_t)kk * (EE / 4)];
            FMA2(acc01, cv2, pr.x);
            FMA2(acc23, cv2, pr.y);
            FMA2(acc01, sv2, pi.x);
            FMA2(acc23, sv2, pi.y);
        }
        __syncthreads();
    }
    float acc[4];
    UNPACK2(acc[0], acc[1], acc01);
    UNPACK2(acc[2], acc[3], acc23);
    __nv_bfloat16 hi[4], lo[4];
#pragma unroll
    for (int q = 0; q < 4; q++) {
        float v = 0.01f * acc[q];
        hi[q] = __float2bfloat16(v);
        lo[q] = __float2bfloat16(v - __bfloat162float(hi[q]));
    }
    int e = e0 + e4 * 4;
    uint32_t loc = SWZ((uint32_t)(n * 128 + (e & 63) * 2));
    char* base = (char*)g_x2a;
    *reinterpret_cast<uint2*>(base + (size_t)(e >> 6) * ASLAB + loc) =
        *reinterpret_cast<uint2*>(hi);
    *reinterpret_cast<uint2*>(base + (size_t)(4 + (e >> 6)) * ASLAB + loc) =
        *reinterpret_cast<uint2*>(lo);
}

// ---------------- launch ----------------
extern "C" void kernel_launch(void* const* d_in, const int* in_sizes, int n_in,
                              void* d_out, int out_size) {
    const float *h = nullptr, *x = nullptr, *kv = nullptr;
    const float *Wpre = nullptr, *Wdn = nullptr, *Wup = nullptr;
    const float *W0 = nullptr, *Wres = nullptr;
    const int* seg = nullptr;

    for (int i = 0; i < n_in; i++) {
        switch (in_sizes[i]) {
            case NN * EE:           h    = (const float*)d_in[i]; break;
            case NN * 3:            x    = (const float*)d_in[i]; break;
            case BB * KK * 3:       kv   = (const float*)d_in[i]; break;
            case NN:                seg  = (const int*)d_in[i];   break;
            case 2 * EE * EE:       Wpre = (const float*)d_in[i]; break;
            case DD * KK:           Wdn  = (const float*)d_in[i]; break;
            case EE * DD:           Wup  = (const float*)d_in[i]; break;
            case EE * EE:           W0   = (const float*)d_in[i]; break;
            case 3 * 2 * EE * EE:   Wres = (const float*)d_in[i]; break;
            default: break;
        }
    }

    float* out = (float*)d_out;
    float* out_hu  = out;            // (NN, EE)
    float* out_dot = out + NN * EE;  // (NN, KK)

    float *t0, *hres;
    __nv_bfloat16 *x2a, *x2b, *wc;
    cudaGetSymbolAddress((void**)&t0,   g_t0);
    cudaGetSymbolAddress((void**)&hres, g_hres);
    cudaGetSymbolAddress((void**)&x2a,  g_x2a);
    cudaGetSymbolAddress((void**)&x2b,  g_x2b);
    cudaGetSymbolAddress((void**)&wc,   g_wc);

    cudaFuncSetAttribute(gemm_mma_kernel,
                         cudaFuncAttributeMaxDynamicSharedMemorySize, GEMM_SMEM);
    dim3 ggrid(EE / 64, NN / 64);  // (4, 64) = 256 CTAs -> 2/SM

    // all independent pre-GEMM work in one launch
    prelude_kernel<<<8592, 256>>>(Wpre, W0, Wres, h, x, kv, seg, Wup, Wdn, out_dot);

    // pre-residual: x2b = silu(h@W0'), hres = h + silu(x2b@W1')
    gemm_mma_kernel<<<ggrid, 256, GEMM_SMEM>>>(x2a, wc + 0 * 131072, nullptr, nullptr, x2b);
    gemm_mma_kernel<<<ggrid, 256, GEMM_SMEM>>>(x2b, wc + 1 * 131072, h, hres, nullptr);

    // structure factors (k64 x e32 tiles) + back-projection
    sf_kernel<<<dim3(EE / 32, KK / 64, BB), 256>>>();
    hupd_kernel<<<dim3(EE / 32, NN / 32), 256>>>(seg);  // -> g_x2a (slabbed hi/lo)

    // update MLP: t0 = silu(hu @ W0^T)
    gemm_mma_kernel<<<ggrid, 256, GEMM_SMEM>>>(x2a, wc + 2 * 131072, nullptr, t0, x2b);

    // 3 residual blocks
    for (int i = 0; i < 3; i++) {
        const __nv_bfloat16* wa = wc + (size_t)(3 + 2 * i) * 131072;
        const __nv_bfloat16* wb = wc + (size_t)(4 + 2 * i) * 131072;
        gemm_mma_kernel<<<ggrid, 256, GEMM_SMEM>>>(x2b, wa, nullptr, nullptr, x2a);
        float* dstf = (i == 2) ? out_hu : t0;
        __nv_bfloat16* dst2 = (i == 2) ? nullptr : x2b;
        gemm_mma_kernel<<<ggrid, 256, GEMM_SMEM>>>(x2a, wb, t0, dstf, dst2);
    }
}